// round 1
// baseline (speedup 1.0000x reference)
#include <cuda_runtime.h>
#include <math.h>

// ---------------- problem constants ----------------
#define NB    2048
#define CIN   16
#define TT    8
#define VMD   42                    // V*M
#define COUT  64
#define NNODE (NB*TT*VMD)           // 688128
#define EINC  (4*NNODE)             // 2752512
#define EMB   336
#define ROWS  (NB*TT)               // 16384
#define OUTW  (8*EMB)               // 2688
#define NE64  (NNODE*64)            // 44040192

// ---------------- scratch (device globals; no mallocs allowed) ----------------
__device__ float  g_xt[NE64];
__device__ float  g_e [NE64];
__device__ float  g_h [NE64];
__device__ float  g_D [NNODE];
__device__ float  g_B [NNODE];
__device__ float  g_xb[NB*TT*VMD*CIN];   // BN-normalized x, layout ((n*8+s)*42+vm)*16+c
__device__ float  g_seq[ROWS*EMB];
__device__ float  g_qq [ROWS*EMB];
__device__ float  g_kk [ROWS*EMB];
__device__ float  g_vv [ROWS*EMB];
__device__ float  g_ao [ROWS*EMB];
__device__ float  g_o2 [ROWS*EMB];
__device__ float  g_Wc [3*EMB*EMB];
__device__ float  g_bc [3*EMB];
__device__ double g_sum[CIN], g_sum2[CIN];
__device__ float  g_scale[CIN], g_shift[CIN];

// ---------------- init ----------------
__global__ void k_zero() {
    int i = blockIdx.x*blockDim.x + threadIdx.x;
    if (i < NE64) { g_e[i] = 0.f; g_h[i] = 0.f; }
    if (i < NNODE) { g_D[i] = 0.f; g_B[i] = 0.f; }
    if (i < CIN) { g_sum[i] = 0.0; g_sum2[i] = 0.0; }
}

// ---------------- BatchNorm stats ----------------
__global__ void k_bnstats(const float* __restrict__ x) {
    __shared__ double sh[128], sh2[128];
    int b = blockIdx.x;                   // n*16+c
    const float* p = x + b*336;
    double s = 0.0, s2 = 0.0;
    for (int i = threadIdx.x; i < 336; i += 128) { double v = p[i]; s += v; s2 += v*v; }
    sh[threadIdx.x] = s; sh2[threadIdx.x] = s2; __syncthreads();
    for (int o = 64; o > 0; o >>= 1) {
        if (threadIdx.x < o) { sh[threadIdx.x] += sh[threadIdx.x+o]; sh2[threadIdx.x] += sh2[threadIdx.x+o]; }
        __syncthreads();
    }
    if (threadIdx.x == 0) {
        int c = b & 15;
        atomicAdd(&g_sum[c], sh[0]);
        atomicAdd(&g_sum2[c], sh2[0]);
    }
}

__global__ void k_bnfin(const float* __restrict__ gamma, const float* __restrict__ beta) {
    int c = threadIdx.x;
    if (c >= CIN) return;
    double cnt = (double)NB * TT * VMD;
    double mean = g_sum[c] / cnt;
    double var  = g_sum2[c] / cnt - mean*mean;
    float sc = gamma[c] * rsqrtf((float)var + 1e-5f);
    g_scale[c] = sc;
    g_shift[c] = beta[c] - (float)mean * sc;
}

// normalized x staged as g_xb[((n*8+s)*42+vm)*16 + c]
__global__ void k_bnx(const float* __restrict__ x) {
    int i = blockIdx.x*blockDim.x + threadIdx.x;
    if (i >= NB*TT*VMD*CIN) return;
    int c = i & 15;
    int r = i >> 4;                 // (n*8+s)*42+vm
    int n = r / 336, rem = r % 336; // rem = s*42+vm
    float v = x[(n*16 + c)*336 + rem];
    g_xb[i] = v * g_scale[c] + g_shift[c];
}

// ---------------- hypergraph conv ----------------
__global__ void k_xt(const float* __restrict__ x, const float* __restrict__ hcw) {
    int i = blockIdx.x*blockDim.x + threadIdx.x;
    if (i >= NE64) return;
    int node = i >> 6, co = i & 63;
    int n = node / 336, rem = node % 336;      // rem = t*42+vm
    const float* xp = x + n*16*336 + rem;      // x[(n*16+c)*336+rem]
    float acc = 0.f;
    #pragma unroll
    for (int c = 0; c < 16; c++) acc += hcw[co*16+c] * xp[c*336];
    g_xt[i] = acc;
}

__global__ void k_deg(const int* __restrict__ hi) {
    int i = blockIdx.x*blockDim.x + threadIdx.x;
    if (i >= EINC) return;
    atomicAdd(&g_D[hi[i]], 1.f);
    atomicAdd(&g_B[hi[EINC + i]], 1.f);
}

__global__ void k_scatter_e(const int* __restrict__ hi) {
    unsigned gi = blockIdx.x*blockDim.x + threadIdx.x;
    if (gi >= (unsigned)EINC * 64u) return;
    int i = (int)(gi >> 6), c = (int)(gi & 63u);
    int node = hi[i], edge = hi[EINC + i];
    float b = g_B[edge];
    float w = (b > 0.f) ? (1.f / b) : 0.f;
    atomicAdd(&g_e[edge*64 + c], w * g_xt[node*64 + c]);
}

__global__ void k_scatter_h(const int* __restrict__ hi) {
    unsigned gi = blockIdx.x*blockDim.x + threadIdx.x;
    if (gi >= (unsigned)EINC * 64u) return;
    int i = (int)(gi >> 6), c = (int)(gi & 63u);
    int node = hi[i], edge = hi[EINC + i];
    float d = g_D[node];
    float w = (d > 0.f) ? (1.f / d) : 0.f;
    atomicAdd(&g_h[node*64 + c], w * g_e[edge*64 + c]);
}

// ---------------- time-conv (::8 slice) -> seq ----------------
// seq[n][o][w*42+vm] = conv_b[o] + sum_t conv_w[o][t]*(h_flat[((n*64+8w)*8+t)*42+vm] + hc_b[(t*42+vm)&63])
__global__ void k_seq(const float* __restrict__ cw, const float* __restrict__ cb,
                      const float* __restrict__ hcb) {
    int i = blockIdx.x*blockDim.x + threadIdx.x;
    if (i >= ROWS*EMB) return;
    int n = i / 2688;
    int r = i % 2688;
    int o = r / 336;
    int q = r % 336;
    int w = q / 42, vm = q % 42;
    const float* hp = g_h + ((n*64 + 8*w)*8)*42 + vm;
    float acc = cb[o];
    #pragma unroll
    for (int t = 0; t < 8; t++) {
        float hv = hp[t*42] + hcb[(t*42 + vm) & 63];
        acc += cw[o*8 + t] * hv;
    }
    g_seq[i] = acc;
}

// ---------------- weight folding: Wc = W1 @ wq ; bc = W1 @ bq + b1 ----------------
__global__ void k_cw(const float* __restrict__ W1, const float* __restrict__ wq,
                     float* __restrict__ Wc) {
    int i = blockIdx.x*blockDim.x + threadIdx.x;
    if (i >= EMB*EMB) return;
    int o = i / EMB, ii = i % EMB;
    float acc = 0.f;
    for (int m = 0; m < EMB; m++) acc += W1[o*EMB + m] * wq[m*EMB + ii];
    Wc[i] = acc;
}

__global__ void k_cb(const float* __restrict__ W1, const float* __restrict__ b1,
                     const float* __restrict__ bq, float* __restrict__ bc) {
    int o = blockIdx.x*blockDim.x + threadIdx.x;
    if (o >= EMB) return;
    float acc = b1[o];
    for (int m = 0; m < EMB; m++) acc += W1[o*EMB + m] * bq[m];
    bc[o] = acc;
}

// ---------------- generic SGEMM: C[m][n] = sum_k A[m][k]*B[n][k] + bias[n] ----------------
__global__ void k_gemm(const float* __restrict__ A, const float* __restrict__ B,
                       const float* __restrict__ bias, float* __restrict__ C,
                       int Nn, int K) {
    __shared__ float As[16][64];
    __shared__ float Bs[16][64];
    const int tid = threadIdx.x;
    const int tx = tid & 15, ty = tid >> 4;
    const int row0 = blockIdx.y << 6, col0 = blockIdx.x << 6;
    const int lm = tid >> 2, lk = (tid & 3) << 2;
    const float* Ap = A + (row0 + lm)*K + lk;
    const bool bval = (col0 + lm) < Nn;
    const float* Bp = B + (col0 + lm)*K + lk;
    float acc[4][4] = {};
    for (int kk = 0; kk < K; kk += 16) {
        float4 a4 = *(const float4*)(Ap + kk);
        float4 b4 = bval ? *(const float4*)(Bp + kk) : make_float4(0.f,0.f,0.f,0.f);
        As[lk+0][lm]=a4.x; As[lk+1][lm]=a4.y; As[lk+2][lm]=a4.z; As[lk+3][lm]=a4.w;
        Bs[lk+0][lm]=b4.x; Bs[lk+1][lm]=b4.y; Bs[lk+2][lm]=b4.z; Bs[lk+3][lm]=b4.w;
        __syncthreads();
        #pragma unroll
        for (int k = 0; k < 16; k++) {
            float4 av = *(const float4*)(&As[k][ty<<2]);
            float4 bv = *(const float4*)(&Bs[k][tx<<2]);
            acc[0][0]+=av.x*bv.x; acc[0][1]+=av.x*bv.y; acc[0][2]+=av.x*bv.z; acc[0][3]+=av.x*bv.w;
            acc[1][0]+=av.y*bv.x; acc[1][1]+=av.y*bv.y; acc[1][2]+=av.y*bv.z; acc[1][3]+=av.y*bv.w;
            acc[2][0]+=av.z*bv.x; acc[2][1]+=av.z*bv.y; acc[2][2]+=av.z*bv.z; acc[2][3]+=av.z*bv.w;
            acc[3][0]+=av.w*bv.x; acc[3][1]+=av.w*bv.y; acc[3][2]+=av.w*bv.z; acc[3][3]+=av.w*bv.w;
        }
        __syncthreads();
    }
    #pragma unroll
    for (int i = 0; i < 4; i++) {
        int r = row0 + (ty<<2) + i;
        #pragma unroll
        for (int j = 0; j < 4; j++) {
            int cc = col0 + (tx<<2) + j;
            if (cc < Nn) C[r*Nn + cc] = acc[i][j] + bias[cc];
        }
    }
}

// ---------------- fc GEMM (K=336, N=2688) + fused residual(BN->proj) + relu ----------------
__global__ void k_gemm_fc(const float* __restrict__ A, const float* __restrict__ B,
                          const float* __restrict__ fcb, const float* __restrict__ pw,
                          const float* __restrict__ pb, float* __restrict__ C) {
    __shared__ float As[16][64];
    __shared__ float Bs[16][64];
    __shared__ float s_pw[64*16];
    const int tid = threadIdx.x;
    for (int i = tid; i < 64*16; i += 256) s_pw[i] = pw[i];
    const int tx = tid & 15, ty = tid >> 4;
    const int row0 = blockIdx.y << 6, col0 = blockIdx.x << 6;
    const int lm = tid >> 2, lk = (tid & 3) << 2;
    const float* Ap = A + (row0 + lm)*336 + lk;
    const float* Bp = B + (col0 + lm)*336 + lk;
    float acc[4][4] = {};
    for (int kk = 0; kk < 336; kk += 16) {
        float4 a4 = *(const float4*)(Ap + kk);
        float4 b4 = *(const float4*)(Bp + kk);
        As[lk+0][lm]=a4.x; As[lk+1][lm]=a4.y; As[lk+2][lm]=a4.z; As[lk+3][lm]=a4.w;
        Bs[lk+0][lm]=b4.x; Bs[lk+1][lm]=b4.y; Bs[lk+2][lm]=b4.z; Bs[lk+3][lm]=b4.w;
        __syncthreads();
        #pragma unroll
        for (int k = 0; k < 16; k++) {
            float4 av = *(const float4*)(&As[k][ty<<2]);
            float4 bv = *(const float4*)(&Bs[k][tx<<2]);
            acc[0][0]+=av.x*bv.x; acc[0][1]+=av.x*bv.y; acc[0][2]+=av.x*bv.z; acc[0][3]+=av.x*bv.w;
            acc[1][0]+=av.y*bv.x; acc[1][1]+=av.y*bv.y; acc[1][2]+=av.y*bv.z; acc[1][3]+=av.y*bv.w;
            acc[2][0]+=av.z*bv.x; acc[2][1]+=av.z*bv.y; acc[2][2]+=av.z*bv.z; acc[2][3]+=av.z*bv.w;
            acc[3][0]+=av.w*bv.x; acc[3][1]+=av.w*bv.y; acc[3][2]+=av.w*bv.z; acc[3][3]+=av.w*bv.w;
        }
        __syncthreads();
    }
    const int vm = col0 >> 6;   // col block == vm (OUTW = 42*64)
    #pragma unroll
    for (int i = 0; i < 4; i++) {
        int m = row0 + (ty<<2) + i;             // m = n*8+s
        const float* xr = g_xb + (m*42 + vm)*16;
        #pragma unroll
        for (int j = 0; j < 4; j++) {
            int jj = col0 + (tx<<2) + j;
            int co = jj & 63;
            float r = pb[co];
            #pragma unroll
            for (int c = 0; c < 16; c++) r += s_pw[co*16 + c] * xr[c];
            float v = acc[i][j] + fcb[jj] + r;
            C[m*2688 + jj] = fmaxf(v, 0.f);
        }
    }
}

// ---------------- attention: one block per (n, head), 64 threads ----------------
__global__ void k_attn() {
    __shared__ float sc[64], at[64];
    const int n = blockIdx.x, h = blockIdx.y;
    const float* Q  = g_qq + n*8*EMB + h*84;
    const float* Kp = g_kk + n*8*EMB + h*84;
    const float* Vp = g_vv + n*8*EMB + h*84;
    float*       AO = g_ao + n*8*EMB + h*84;
    const int tid = threadIdx.x, s = tid >> 3, t = tid & 7;
    float acc = 0.f;
    #pragma unroll 4
    for (int d = 0; d < 84; d++) acc += Q[s*EMB + d] * Kp[t*EMB + d];
    sc[tid] = acc * 0.1091089451179961805f;   // 1/sqrt(84)
    __syncthreads();
    float mx = sc[s*8];
    #pragma unroll
    for (int k = 1; k < 8; k++) mx = fmaxf(mx, sc[s*8 + k]);
    float e = expf(sc[tid] - mx);
    at[tid] = e;
    __syncthreads();
    float sum = 0.f;
    #pragma unroll
    for (int k = 0; k < 8; k++) sum += at[s*8 + k];
    float a = e / sum;
    __syncthreads();
    at[tid] = a;
    __syncthreads();
    for (int idx = tid; idx < 672; idx += 64) {
        int ss = idx / 84, d = idx - ss*84;
        float o = 0.f;
        #pragma unroll
        for (int k = 0; k < 8; k++) o += at[ss*8 + k] * Vp[k*EMB + d];
        AO[ss*EMB + d] = o;
    }
}

// ---------------- launcher ----------------
extern "C" void kernel_launch(void* const* d_in, const int* in_sizes, int n_in,
                              void* d_out, int out_size) {
    const float* x   = (const float*)d_in[0];
    const int*   hi  = (const int*)  d_in[1];
    const float* hcw = (const float*)d_in[2];
    const float* hcb = (const float*)d_in[3];
    const float* cw  = (const float*)d_in[4];
    const float* cb  = (const float*)d_in[5];
    const float* gam = (const float*)d_in[6];
    const float* bet = (const float*)d_in[7];
    const float* pw  = (const float*)d_in[8];
    const float* pb  = (const float*)d_in[9];
    const float* wq  = (const float*)d_in[10];
    const float* bq  = (const float*)d_in[11];
    const float* wk  = (const float*)d_in[12];
    const float* bk  = (const float*)d_in[13];
    const float* wv  = (const float*)d_in[14];
    const float* bv  = (const float*)d_in[15];
    const float* ipw = (const float*)d_in[16];
    const float* ipb = (const float*)d_in[17];
    const float* opw = (const float*)d_in[18];
    const float* opb = (const float*)d_in[19];
    const float* fw  = (const float*)d_in[20];
    const float* fb  = (const float*)d_in[21];
    float* out = (float*)d_out;

    float *p_seq, *p_qq, *p_kk, *p_vv, *p_ao, *p_o2, *p_Wc, *p_bc;
    cudaGetSymbolAddress((void**)&p_seq, g_seq);
    cudaGetSymbolAddress((void**)&p_qq,  g_qq);
    cudaGetSymbolAddress((void**)&p_kk,  g_kk);
    cudaGetSymbolAddress((void**)&p_vv,  g_vv);
    cudaGetSymbolAddress((void**)&p_ao,  g_ao);
    cudaGetSymbolAddress((void**)&p_o2,  g_o2);
    cudaGetSymbolAddress((void**)&p_Wc,  g_Wc);
    cudaGetSymbolAddress((void**)&p_bc,  g_bc);

    // 1) zero scratch
    k_zero<<<(NE64 + 255)/256, 256>>>();
    // 2) BN stats + finalize + staged normalized x
    k_bnstats<<<NB*CIN, 128>>>(x);
    k_bnfin<<<1, 32>>>(gam, bet);
    k_bnx<<<(NB*TT*VMD*CIN + 255)/256, 256>>>(x);
    // 3) hypergraph conv
    k_xt<<<(NE64 + 255)/256, 256>>>(x, hcw);
    k_deg<<<(EINC + 255)/256, 256>>>(hi);
    k_scatter_e<<<(unsigned)(((long long)EINC*64 + 255)/256), 256>>>(hi);
    k_scatter_h<<<(unsigned)(((long long)EINC*64 + 255)/256), 256>>>(hi);
    // 4) time conv -> seq
    k_seq<<<(ROWS*EMB + 255)/256, 256>>>(cw, cb, hcb);
    // 5) fold q/k/v projection pairs
    k_cw<<<(EMB*EMB + 255)/256, 256>>>(ipw,             wq, p_Wc);
    k_cw<<<(EMB*EMB + 255)/256, 256>>>(ipw +   EMB*EMB, wk, p_Wc +   EMB*EMB);
    k_cw<<<(EMB*EMB + 255)/256, 256>>>(ipw + 2*EMB*EMB, wv, p_Wc + 2*EMB*EMB);
    k_cb<<<2, 256>>>(ipw,             ipb,         bq, p_bc);
    k_cb<<<2, 256>>>(ipw +   EMB*EMB, ipb +   EMB, bk, p_bc + EMB);
    k_cb<<<2, 256>>>(ipw + 2*EMB*EMB, ipb + 2*EMB, bv, p_bc + 2*EMB);
    // 6) qq/kk/vv GEMMs
    dim3 g336((EMB + 63)/64, ROWS/64);
    k_gemm<<<g336, 256>>>(p_seq, p_Wc,             p_bc,         p_qq, EMB, EMB);
    k_gemm<<<g336, 256>>>(p_seq, p_Wc +   EMB*EMB, p_bc + EMB,   p_kk, EMB, EMB);
    k_gemm<<<g336, 256>>>(p_seq, p_Wc + 2*EMB*EMB, p_bc + 2*EMB, p_vv, EMB, EMB);
    // 7) attention
    k_attn<<<dim3(NB, 4), 64>>>();
    // 8) out_proj
    k_gemm<<<g336, 256>>>(p_ao, opw, opb, p_o2, EMB, EMB);
    // 9) fc + fused residual + relu
    dim3 gfc(OUTW/64, ROWS/64);
    k_gemm_fc<<<gfc, 256>>>(p_o2, fw, fb, pw, pb, out);
}

// round 2
// speedup vs baseline: 1.4290x; 1.4290x over previous
#include <cuda_runtime.h>
#include <math.h>

#define NB    2048
#define CIN   16
#define TT    8
#define VMD   42
#define NNODE (NB*TT*VMD)           // 688128
#define EINC  (4*NNODE)             // 2752512
#define EMB   336
#define ROWS  (NB*TT)               // 16384
#define OUTW  (8*EMB)               // 2688
#define NE64  (NNODE*64)            // 44040192

// ---------------- scratch ----------------
__device__ __align__(16) float  g_xt[NE64];
__device__ __align__(16) float  g_e [NE64];
__device__ __align__(16) float  g_h [NE64];
__device__ __align__(16) float  g_D [NNODE];
__device__ __align__(16) float  g_B [NNODE];
__device__ __align__(16) float  g_xb[NNODE*CIN];
__device__ __align__(16) float  g_seq[ROWS*EMB];
__device__ __align__(16) float  g_qkv[ROWS*3*EMB];
__device__ __align__(16) float  g_ao [ROWS*EMB];
__device__ __align__(16) float  g_o2 [ROWS*EMB];
__device__ __align__(16) float  g_Wc [3*EMB*EMB];
__device__ __align__(16) float  g_bc [3*EMB];
__device__ double g_sum[CIN], g_sum2[CIN];
__device__ float  g_scale[CIN], g_shift[CIN];

// ---------------- f32x2 helpers ----------------
__device__ __forceinline__ unsigned long long ffma2(unsigned long long a,
                                                    unsigned long long b,
                                                    unsigned long long c) {
    unsigned long long d;
    asm("fma.rn.f32x2 %0, %1, %2, %3;" : "=l"(d) : "l"(a), "l"(b), "l"(c));
    return d;
}
__device__ __forceinline__ unsigned long long pack2(float x, float y) {
    unsigned long long d;
    asm("mov.b64 %0, {%1, %2};" : "=l"(d) : "f"(x), "f"(y));
    return d;
}
__device__ __forceinline__ float2 unpack2(unsigned long long v) {
    float2 r;
    asm("mov.b64 {%0, %1}, %2;" : "=f"(r.x), "=f"(r.y) : "l"(v));
    return r;
}

// ---------------- init ----------------
__global__ void k_zero() {
    int i = blockIdx.x*blockDim.x + threadIdx.x;
    float4 z = make_float4(0.f,0.f,0.f,0.f);
    if (i < NE64/4) { ((float4*)g_e)[i] = z; ((float4*)g_h)[i] = z; }
    if (i < NNODE) { g_D[i] = 0.f; g_B[i] = 0.f; }
    if (i < CIN) { g_sum[i] = 0.0; g_sum2[i] = 0.0; }
}

// ---------------- BatchNorm ----------------
__global__ void k_bnstats(const float* __restrict__ x) {
    __shared__ double sh[128], sh2[128];
    int b = blockIdx.x;
    const float* p = x + b*336;
    double s = 0.0, s2 = 0.0;
    for (int i = threadIdx.x; i < 336; i += 128) { double v = p[i]; s += v; s2 += v*v; }
    sh[threadIdx.x] = s; sh2[threadIdx.x] = s2; __syncthreads();
    for (int o = 64; o > 0; o >>= 1) {
        if (threadIdx.x < o) { sh[threadIdx.x] += sh[threadIdx.x+o]; sh2[threadIdx.x] += sh2[threadIdx.x+o]; }
        __syncthreads();
    }
    if (threadIdx.x == 0) {
        int c = b & 15;
        atomicAdd(&g_sum[c], sh[0]);
        atomicAdd(&g_sum2[c], sh2[0]);
    }
}

__global__ void k_bnfin(const float* __restrict__ gamma, const float* __restrict__ beta) {
    int c = threadIdx.x;
    if (c >= CIN) return;
    double cnt = (double)NB * TT * VMD;
    double mean = g_sum[c] / cnt;
    double var  = g_sum2[c] / cnt - mean*mean;
    float sc = gamma[c] * rsqrtf((float)var + 1e-5f);
    g_scale[c] = sc;
    g_shift[c] = beta[c] - (float)mean * sc;
}

__global__ void k_bnx(const float* __restrict__ x) {
    int i = blockIdx.x*blockDim.x + threadIdx.x;
    if (i >= NNODE*CIN) return;
    int c = i & 15;
    int r = i >> 4;
    int n = r / 336, rem = r % 336;
    float v = x[(n*16 + c)*336 + rem];
    g_xb[i] = v * g_scale[c] + g_shift[c];
}

// ---------------- hypergraph conv ----------------
__global__ void k_xt(const float* __restrict__ x, const float* __restrict__ hcw) {
    int i = blockIdx.x*blockDim.x + threadIdx.x;   // NNODE*16
    if (i >= NNODE*16) return;
    int node = i >> 4, c4 = (i & 15) << 2;
    int n = node / 336, rem = node % 336;
    const float* xp = x + n*16*336 + rem;
    float4 acc = make_float4(0.f,0.f,0.f,0.f);
    #pragma unroll
    for (int c = 0; c < 16; c++) {
        float xv = __ldg(xp + c*336);
        acc.x += hcw[(c4+0)*16+c]*xv;
        acc.y += hcw[(c4+1)*16+c]*xv;
        acc.z += hcw[(c4+2)*16+c]*xv;
        acc.w += hcw[(c4+3)*16+c]*xv;
    }
    *(float4*)(g_xt + (size_t)node*64 + c4) = acc;
}

__global__ void k_deg(const int* __restrict__ hi) {
    int i = blockIdx.x*blockDim.x + threadIdx.x;
    if (i >= EINC) return;
    atomicAdd(&g_D[hi[i]], 1.f);
    atomicAdd(&g_B[hi[EINC + i]], 1.f);
}

__global__ void k_inv() {
    int i = blockIdx.x*blockDim.x + threadIdx.x;
    if (i >= NNODE) return;
    float d = g_D[i]; g_D[i] = (d > 0.f) ? (1.f/d) : 0.f;
    float b = g_B[i]; g_B[i] = (b > 0.f) ? (1.f/b) : 0.f;
}

__global__ void k_scatter_e(const int* __restrict__ hi) {
    unsigned gi = blockIdx.x*blockDim.x + threadIdx.x;   // EINC*16
    if (gi >= (unsigned)EINC * 16u) return;
    int i = (int)(gi >> 4), g = (int)((gi & 15u) << 2);
    int node = __ldg(&hi[i]), edge = __ldg(&hi[EINC + i]);
    float w = g_B[edge];
    float4 v = *(const float4*)(g_xt + (size_t)node*64 + g);
    v.x *= w; v.y *= w; v.z *= w; v.w *= w;
    float* dst = g_e + (size_t)edge*64 + g;
    asm volatile("red.global.add.v4.f32 [%0], {%1, %2, %3, %4};"
                 :: "l"(dst), "f"(v.x), "f"(v.y), "f"(v.z), "f"(v.w) : "memory");
}

__global__ void k_scatter_h(const int* __restrict__ hi) {
    unsigned gi = blockIdx.x*blockDim.x + threadIdx.x;   // EINC*16
    if (gi >= (unsigned)EINC * 16u) return;
    int i = (int)(gi >> 4), g = (int)((gi & 15u) << 2);
    int node = __ldg(&hi[i]), edge = __ldg(&hi[EINC + i]);
    float w = g_D[node];
    float4 v = *(const float4*)(g_e + (size_t)edge*64 + g);
    v.x *= w; v.y *= w; v.z *= w; v.w *= w;
    float* dst = g_h + (size_t)node*64 + g;
    asm volatile("red.global.add.v4.f32 [%0], {%1, %2, %3, %4};"
                 :: "l"(dst), "f"(v.x), "f"(v.y), "f"(v.z), "f"(v.w) : "memory");
}

// ---------------- time-conv -> seq ----------------
__global__ void k_seq(const float* __restrict__ cw, const float* __restrict__ cb,
                      const float* __restrict__ hcb) {
    int i = blockIdx.x*blockDim.x + threadIdx.x;
    if (i >= ROWS*EMB) return;
    int n = i / 2688;
    int r = i % 2688;
    int o = r / 336;
    int q = r % 336;
    int w = q / 42, vm = q % 42;
    const float* hp = g_h + ((size_t)(n*64 + 8*w)*8)*42 + vm;
    float acc = cb[o];
    #pragma unroll
    for (int t = 0; t < 8; t++) {
        float hv = hp[t*42] + hcb[(t*42 + vm) & 63];
        acc += cw[o*8 + t] * hv;
    }
    g_seq[i] = acc;
}

// ---------------- weight folding ----------------
__global__ void k_cw(const float* __restrict__ W1, const float* __restrict__ wq,
                     float* __restrict__ Wc) {
    int i = blockIdx.x*blockDim.x + threadIdx.x;
    if (i >= EMB*EMB) return;
    int o = i / EMB, ii = i % EMB;
    float acc = 0.f;
    for (int m = 0; m < EMB; m++) acc += W1[o*EMB + m] * wq[m*EMB + ii];
    Wc[i] = acc;
}

__global__ void k_cb(const float* __restrict__ W1, const float* __restrict__ b1,
                     const float* __restrict__ bq, float* __restrict__ bc) {
    int o = blockIdx.x*blockDim.x + threadIdx.x;
    if (o >= EMB) return;
    float acc = b1[o];
    for (int m = 0; m < EMB; m++) acc += W1[o*EMB + m] * bq[m];
    bc[o] = acc;
}

// ---------------- 128x128 f32x2 SGEMM: C[m][n] = A[m][:]·B[n][:] + bias[n] ----------------
#define ROWFMA(RR, AV) { unsigned long long aa = pack2(AV, AV); \
    acc2[RR][0] = ffma2(aa, bq0.x, acc2[RR][0]); \
    acc2[RR][1] = ffma2(aa, bq0.y, acc2[RR][1]); \
    acc2[RR][2] = ffma2(aa, bq1.x, acc2[RR][2]); \
    acc2[RR][3] = ffma2(aa, bq1.y, acc2[RR][3]); }

__global__ __launch_bounds__(256) void k_gemm128(
        const float* __restrict__ A, const float* __restrict__ B,
        const float* __restrict__ bias, float* __restrict__ C,
        int Nn, int K) {
    __shared__ __align__(16) float As[2][16][128];
    __shared__ __align__(16) float Bs[2][16][128];
    const int tid = threadIdx.x;
    const int row0 = blockIdx.y << 7, col0 = blockIdx.x << 7;
    const int lr = tid >> 2;
    const int lk = (tid & 3) << 2;
    const int tx = tid & 15, ty = tid >> 4;
    const float* Ap  = A + (size_t)(row0 + lr)*K + lk;
    const float* Ap2 = Ap + (size_t)64*K;
    const int br0 = col0 + lr, br1 = br0 + 64;
    const bool v0 = br0 < Nn, v1 = br1 < Nn;
    const float* Bp0 = B + (size_t)(v0 ? br0 : 0)*K + lk;
    const float* Bp1 = B + (size_t)(v1 ? br1 : 0)*K + lk;
    const float4 z = make_float4(0.f,0.f,0.f,0.f);
    float4 pa0 = *(const float4*)Ap;
    float4 pa1 = *(const float4*)Ap2;
    float4 pb0 = v0 ? *(const float4*)Bp0 : z;
    float4 pb1 = v1 ? *(const float4*)Bp1 : z;
    unsigned long long acc2[8][4];
    #pragma unroll
    for (int i = 0; i < 8; i++)
        #pragma unroll
        for (int j = 0; j < 4; j++) acc2[i][j] = 0ull;

    As[0][lk+0][lr]=pa0.x; As[0][lk+1][lr]=pa0.y; As[0][lk+2][lr]=pa0.z; As[0][lk+3][lr]=pa0.w;
    As[0][lk+0][lr+64]=pa1.x; As[0][lk+1][lr+64]=pa1.y; As[0][lk+2][lr+64]=pa1.z; As[0][lk+3][lr+64]=pa1.w;
    Bs[0][lk+0][lr]=pb0.x; Bs[0][lk+1][lr]=pb0.y; Bs[0][lk+2][lr]=pb0.z; Bs[0][lk+3][lr]=pb0.w;
    Bs[0][lk+0][lr+64]=pb1.x; Bs[0][lk+1][lr+64]=pb1.y; Bs[0][lk+2][lr+64]=pb1.z; Bs[0][lk+3][lr+64]=pb1.w;
    __syncthreads();

    int buf = 0;
    #pragma unroll 1
    for (int kk = 16; kk <= K; kk += 16) {
        if (kk < K) {
            pa0 = *(const float4*)(Ap + kk);
            pa1 = *(const float4*)(Ap2 + kk);
            pb0 = v0 ? *(const float4*)(Bp0 + kk) : z;
            pb1 = v1 ? *(const float4*)(Bp1 + kk) : z;
        }
        #pragma unroll
        for (int k = 0; k < 16; k++) {
            float4 a0 = *(const float4*)&As[buf][k][ty<<3];
            float4 a1 = *(const float4*)&As[buf][k][(ty<<3)+4];
            ulonglong2 bq0 = *(const ulonglong2*)&Bs[buf][k][tx<<3];
            ulonglong2 bq1 = *(const ulonglong2*)&Bs[buf][k][(tx<<3)+4];
            ROWFMA(0, a0.x) ROWFMA(1, a0.y) ROWFMA(2, a0.z) ROWFMA(3, a0.w)
            ROWFMA(4, a1.x) ROWFMA(5, a1.y) ROWFMA(6, a1.z) ROWFMA(7, a1.w)
        }
        if (kk < K) {
            int nb = buf ^ 1;
            As[nb][lk+0][lr]=pa0.x; As[nb][lk+1][lr]=pa0.y; As[nb][lk+2][lr]=pa0.z; As[nb][lk+3][lr]=pa0.w;
            As[nb][lk+0][lr+64]=pa1.x; As[nb][lk+1][lr+64]=pa1.y; As[nb][lk+2][lr+64]=pa1.z; As[nb][lk+3][lr+64]=pa1.w;
            Bs[nb][lk+0][lr]=pb0.x; Bs[nb][lk+1][lr]=pb0.y; Bs[nb][lk+2][lr]=pb0.z; Bs[nb][lk+3][lr]=pb0.w;
            Bs[nb][lk+0][lr+64]=pb1.x; Bs[nb][lk+1][lr+64]=pb1.y; Bs[nb][lk+2][lr+64]=pb1.z; Bs[nb][lk+3][lr+64]=pb1.w;
        }
        __syncthreads();
        buf ^= 1;
    }

    const int cc = col0 + (tx << 3);
    if (cc < Nn) {
        float4 bb0 = *(const float4*)(bias + cc);
        float4 bb1 = *(const float4*)(bias + cc + 4);
        #pragma unroll
        for (int i = 0; i < 8; i++) {
            int r = row0 + (ty << 3) + i;
            float2 u0 = unpack2(acc2[i][0]);
            float2 u1 = unpack2(acc2[i][1]);
            float2 u2 = unpack2(acc2[i][2]);
            float2 u3 = unpack2(acc2[i][3]);
            float4 o0 = make_float4(u0.x+bb0.x, u0.y+bb0.y, u1.x+bb0.z, u1.y+bb0.w);
            float4 o1 = make_float4(u2.x+bb1.x, u2.y+bb1.y, u3.x+bb1.z, u3.y+bb1.w);
            *(float4*)(C + (size_t)r*Nn + cc)     = o0;
            *(float4*)(C + (size_t)r*Nn + cc + 4) = o1;
        }
    }
}

// ---------------- fc GEMM (M=16384, N=2688, K=336) + fused residual + relu ----------------
__global__ __launch_bounds__(256) void k_gemm_fc(
        const float* __restrict__ A, const float* __restrict__ B,
        const float* __restrict__ fcb, const float* __restrict__ pw,
        const float* __restrict__ pb, float* __restrict__ C) {
    __shared__ __align__(16) float As[2][16][128];
    __shared__ __align__(16) float Bs[2][16][128];
    __shared__ __align__(16) float s_pw[16*64];
    __shared__ __align__(16) float s_pb[64];
    const int tid = threadIdx.x;
    for (int i = tid; i < 16*64; i += 256) {
        int c = i >> 6, co = i & 63;
        s_pw[i] = pw[co*16 + c];
    }
    if (tid < 64) s_pb[tid] = pb[tid];

    const int row0 = blockIdx.y << 7, col0 = blockIdx.x << 7;
    const int lr = tid >> 2;
    const int lk = (tid & 3) << 2;
    const int tx = tid & 15, ty = tid >> 4;
    const float* Ap  = A + (size_t)(row0 + lr)*336 + lk;
    const float* Ap2 = Ap + (size_t)64*336;
    const float* Bp0 = B + (size_t)(col0 + lr)*336 + lk;
    const float* Bp1 = Bp0 + (size_t)64*336;
    float4 pa0 = *(const float4*)Ap;
    float4 pa1 = *(const float4*)Ap2;
    float4 pb4a = *(const float4*)Bp0;
    float4 pb4b = *(const float4*)Bp1;
    unsigned long long acc2[8][4];
    #pragma unroll
    for (int i = 0; i < 8; i++)
        #pragma unroll
        for (int j = 0; j < 4; j++) acc2[i][j] = 0ull;

    As[0][lk+0][lr]=pa0.x; As[0][lk+1][lr]=pa0.y; As[0][lk+2][lr]=pa0.z; As[0][lk+3][lr]=pa0.w;
    As[0][lk+0][lr+64]=pa1.x; As[0][lk+1][lr+64]=pa1.y; As[0][lk+2][lr+64]=pa1.z; As[0][lk+3][lr+64]=pa1.w;
    Bs[0][lk+0][lr]=pb4a.x; Bs[0][lk+1][lr]=pb4a.y; Bs[0][lk+2][lr]=pb4a.z; Bs[0][lk+3][lr]=pb4a.w;
    Bs[0][lk+0][lr+64]=pb4b.x; Bs[0][lk+1][lr+64]=pb4b.y; Bs[0][lk+2][lr+64]=pb4b.z; Bs[0][lk+3][lr+64]=pb4b.w;
    __syncthreads();

    int buf = 0;
    #pragma unroll 1
    for (int kk = 16; kk <= 336; kk += 16) {
        if (kk < 336) {
            pa0 = *(const float4*)(Ap + kk);
            pa1 = *(const float4*)(Ap2 + kk);
            pb4a = *(const float4*)(Bp0 + kk);
            pb4b = *(const float4*)(Bp1 + kk);
        }
        #pragma unroll
        for (int k = 0; k < 16; k++) {
            float4 a0 = *(const float4*)&As[buf][k][ty<<3];
            float4 a1 = *(const float4*)&As[buf][k][(ty<<3)+4];
            ulonglong2 bq0 = *(const ulonglong2*)&Bs[buf][k][tx<<3];
            ulonglong2 bq1 = *(const ulonglong2*)&Bs[buf][k][(tx<<3)+4];
            ROWFMA(0, a0.x) ROWFMA(1, a0.y) ROWFMA(2, a0.z) ROWFMA(3, a0.w)
            ROWFMA(4, a1.x) ROWFMA(5, a1.y) ROWFMA(6, a1.z) ROWFMA(7, a1.w)
        }
        if (kk < 336) {
            int nb = buf ^ 1;
            As[nb][lk+0][lr]=pa0.x; As[nb][lk+1][lr]=pa0.y; As[nb][lk+2][lr]=pa0.z; As[nb][lk+3][lr]=pa0.w;
            As[nb][lk+0][lr+64]=pa1.x; As[nb][lk+1][lr+64]=pa1.y; As[nb][lk+2][lr+64]=pa1.z; As[nb][lk+3][lr+64]=pa1.w;
            Bs[nb][lk+0][lr]=pb4a.x; Bs[nb][lk+1][lr]=pb4a.y; Bs[nb][lk+2][lr]=pb4a.z; Bs[nb][lk+3][lr]=pb4a.w;
            Bs[nb][lk+0][lr+64]=pb4b.x; Bs[nb][lk+1][lr+64]=pb4b.y; Bs[nb][lk+2][lr+64]=pb4b.z; Bs[nb][lk+3][lr+64]=pb4b.w;
        }
        __syncthreads();
        buf ^= 1;
    }

    // ---- stage xb rows for residual (alias onto As, now dead) ----
    float* xs = &As[0][0][0];     // 4096 floats: xs[vml*2048 + mr*16 + c]
    const int vm0 = col0 >> 6;
    #pragma unroll 1
    for (int t = tid; t < 4096; t += 256) {
        int vml = t >> 11, mr = (t >> 4) & 127, c = t & 15;
        xs[t < 2048 ? t : t] = 0.f;  // placeholder overwritten below (keeps compiler honest)
        xs[vml*2048 + mr*16 + c] = g_xb[((size_t)(row0 + mr)*42 + vm0 + vml)*16 + c];
    }
    __syncthreads();

    const int cc  = col0 + (tx << 3);
    const int vml = tx >> 3;
    const int cb0 = cc & 63;
    // residual accumulation (packed): acc2 += pw[c][co]*xb[m][vm][c]
    #pragma unroll
    for (int c = 0; c < 16; c++) {
        ulonglong2 w0 = *(const ulonglong2*)&s_pw[c*64 + cb0];
        ulonglong2 w1 = *(const ulonglong2*)&s_pw[c*64 + cb0 + 4];
        #pragma unroll
        for (int i = 0; i < 8; i++) {
            float xvc = xs[vml*2048 + ((ty<<3)+i)*16 + c];
            unsigned long long xx = pack2(xvc, xvc);
            acc2[i][0] = ffma2(xx, w0.x, acc2[i][0]);
            acc2[i][1] = ffma2(xx, w0.y, acc2[i][1]);
            acc2[i][2] = ffma2(xx, w1.x, acc2[i][2]);
            acc2[i][3] = ffma2(xx, w1.y, acc2[i][3]);
        }
    }
    float bsum[8];
    #pragma unroll
    for (int j = 0; j < 8; j++) bsum[j] = fcb[cc + j] + s_pb[cb0 + j];
    #pragma unroll
    for (int i = 0; i < 8; i++) {
        int r = row0 + (ty << 3) + i;
        float2 u0 = unpack2(acc2[i][0]);
        float2 u1 = unpack2(acc2[i][1]);
        float2 u2 = unpack2(acc2[i][2]);
        float2 u3 = unpack2(acc2[i][3]);
        float4 o0 = make_float4(fmaxf(u0.x+bsum[0],0.f), fmaxf(u0.y+bsum[1],0.f),
                                fmaxf(u1.x+bsum[2],0.f), fmaxf(u1.y+bsum[3],0.f));
        float4 o1 = make_float4(fmaxf(u2.x+bsum[4],0.f), fmaxf(u2.y+bsum[5],0.f),
                                fmaxf(u3.x+bsum[6],0.f), fmaxf(u3.y+bsum[7],0.f));
        *(float4*)(C + (size_t)r*2688 + cc)     = o0;
        *(float4*)(C + (size_t)r*2688 + cc + 4) = o1;
    }
}

// ---------------- attention ----------------
__global__ void k_attn() {
    __shared__ float sc[64], at[64];
    const int n = blockIdx.x, h = blockIdx.y;
    const float* Q  = g_qkv + (size_t)n*8*1008 + h*84;
    const float* Kp = Q + 336;
    const float* Vp = Q + 672;
    float*       AO = g_ao + (size_t)n*8*EMB + h*84;
    const int tid = threadIdx.x, s = tid >> 3, t = tid & 7;
    float acc = 0.f;
    #pragma unroll 4
    for (int d = 0; d < 84; d++) acc += Q[s*1008 + d] * Kp[t*1008 + d];
    sc[tid] = acc * 0.1091089451179961805f;   // 1/sqrt(84)
    __syncthreads();
    float mx = sc[s*8];
    #pragma unroll
    for (int k = 1; k < 8; k++) mx = fmaxf(mx, sc[s*8 + k]);
    float e = expf(sc[tid] - mx);
    at[tid] = e;
    __syncthreads();
    float sum = 0.f;
    #pragma unroll
    for (int k = 0; k < 8; k++) sum += at[s*8 + k];
    float a = e / sum;
    __syncthreads();
    at[tid] = a;
    __syncthreads();
    for (int idx = tid; idx < 672; idx += 64) {
        int ss = idx / 84, d = idx - ss*84;
        float o = 0.f;
        #pragma unroll
        for (int k = 0; k < 8; k++) o += at[ss*8 + k] * Vp[k*1008 + d];
        AO[ss*EMB + d] = o;
    }
}

// ---------------- launcher ----------------
extern "C" void kernel_launch(void* const* d_in, const int* in_sizes, int n_in,
                              void* d_out, int out_size) {
    const float* x   = (const float*)d_in[0];
    const int*   hi  = (const int*)  d_in[1];
    const float* hcw = (const float*)d_in[2];
    const float* hcb = (const float*)d_in[3];
    const float* cw  = (const float*)d_in[4];
    const float* cb  = (const float*)d_in[5];
    const float* gam = (const float*)d_in[6];
    const float* bet = (const float*)d_in[7];
    const float* pw  = (const float*)d_in[8];
    const float* pb  = (const float*)d_in[9];
    const float* wq  = (const float*)d_in[10];
    const float* bq  = (const float*)d_in[11];
    const float* wk  = (const float*)d_in[12];
    const float* bk  = (const float*)d_in[13];
    const float* wv  = (const float*)d_in[14];
    const float* bv  = (const float*)d_in[15];
    const float* ipw = (const float*)d_in[16];
    const float* ipb = (const float*)d_in[17];
    const float* opw = (const float*)d_in[18];
    const float* opb = (const float*)d_in[19];
    const float* fw  = (const float*)d_in[20];
    const float* fb  = (const float*)d_in[21];
    float* out = (float*)d_out;
    (void)bk; (void)bv;

    float *p_seq, *p_qkv, *p_ao, *p_o2, *p_Wc, *p_bc;
    cudaGetSymbolAddress((void**)&p_seq, g_seq);
    cudaGetSymbolAddress((void**)&p_qkv, g_qkv);
    cudaGetSymbolAddress((void**)&p_ao,  g_ao);
    cudaGetSymbolAddress((void**)&p_o2,  g_o2);
    cudaGetSymbolAddress((void**)&p_Wc,  g_Wc);
    cudaGetSymbolAddress((void**)&p_bc,  g_bc);

    k_zero<<<(NE64/4 + 255)/256, 256>>>();
    k_bnstats<<<NB*CIN, 128>>>(x);
    k_bnfin<<<1, 32>>>(gam, bet);
    k_bnx<<<(NNODE*CIN + 255)/256, 256>>>(x);
    k_xt<<<(NNODE*16 + 255)/256, 256>>>(x, hcw);
    k_deg<<<(EINC + 255)/256, 256>>>(hi);
    k_inv<<<(NNODE + 255)/256, 256>>>();
    {
        long long tot = (long long)EINC * 16;
        int blocks = (int)((tot + 255) / 256);
        k_scatter_e<<<blocks, 256>>>(hi);
        k_scatter_h<<<blocks, 256>>>(hi);
    }
    k_seq<<<(ROWS*EMB + 255)/256, 256>>>(cw, cb, hcb);
    k_cw<<<(EMB*EMB + 255)/256, 256>>>(ipw,             wq, p_Wc);
    k_cw<<<(EMB*EMB + 255)/256, 256>>>(ipw +   EMB*EMB, wk, p_Wc +   EMB*EMB);
    k_cw<<<(EMB*EMB + 255)/256, 256>>>(ipw + 2*EMB*EMB, wv, p_Wc + 2*EMB*EMB);
    k_cb<<<2, 256>>>(ipw,             ipb,         bq, p_bc);
    k_cb<<<2, 256>>>(ipw +   EMB*EMB, ipb +   EMB, (const float*)d_in[13], p_bc + EMB);
    k_cb<<<2, 256>>>(ipw + 2*EMB*EMB, ipb + 2*EMB, (const float*)d_in[15], p_bc + 2*EMB);

    // qq/kk/vv fused: N = 1008
    dim3 gqkv(8, ROWS/128);
    k_gemm128<<<gqkv, 256>>>(p_seq, p_Wc, p_bc, p_qkv, 3*EMB, EMB);
    k_attn<<<dim3(NB, 4), 64>>>();
    dim3 gop(3, ROWS/128);
    k_gemm128<<<gop, 256>>>(p_ao, opw, opb, p_o2, EMB, EMB);
    dim3 gfc(OUTW/128, ROWS/128);
    k_gemm_fc<<<gfc, 256>>>(p_o2, fw, fb, pw, pb, out);
}

// round 3
// speedup vs baseline: 2.7580x; 1.9300x over previous
#include <cuda_runtime.h>
#include <math.h>

#define NB    2048
#define CIN   16
#define TT    8
#define VMD   42
#define NNODE (NB*TT*VMD)           // 688128
#define EINC  (4*NNODE)             // 2752512
#define EMB   336
#define ROWS  (NB*TT)               // 16384
#define OUTW  (8*EMB)               // 2688
#define NN16  (NNODE*16)            // 11010048

// ---------------- scratch ----------------
__device__ __align__(16) float  g_xn[NN16];      // raw x, node-major [node][c]
__device__ __align__(16) float  g_xb[NN16];      // BN-normalized, node-major
__device__ __align__(16) float  g_e [NN16];
__device__ __align__(16) float  g_h [NN16];
__device__ __align__(16) float  g_D [NNODE];
__device__ __align__(16) float  g_B [NNODE];
__device__ __align__(16) float  g_seq[ROWS*EMB];
__device__ __align__(16) float  g_qkv[ROWS*3*EMB];
__device__ __align__(16) float  g_ao [ROWS*EMB];
__device__ __align__(16) float  g_o2 [ROWS*EMB];
__device__ __align__(16) float  g_Wc [3*EMB*EMB];
__device__ __align__(16) float  g_bc [3*EMB];
__device__ double g_sum[CIN], g_sum2[CIN];
__device__ float  g_scale[CIN], g_shift[CIN];

// ---------------- f32x2 helpers ----------------
__device__ __forceinline__ unsigned long long ffma2(unsigned long long a,
                                                    unsigned long long b,
                                                    unsigned long long c) {
    unsigned long long d;
    asm("fma.rn.f32x2 %0, %1, %2, %3;" : "=l"(d) : "l"(a), "l"(b), "l"(c));
    return d;
}
__device__ __forceinline__ unsigned long long pack2(float x, float y) {
    unsigned long long d;
    asm("mov.b64 %0, {%1, %2};" : "=l"(d) : "f"(x), "f"(y));
    return d;
}
__device__ __forceinline__ float2 unpack2(unsigned long long v) {
    float2 r;
    asm("mov.b64 {%0, %1}, %2;" : "=f"(r.x), "=f"(r.y) : "l"(v));
    return r;
}

// ---------------- init ----------------
__global__ void k_zero() {
    int i = blockIdx.x*blockDim.x + threadIdx.x;
    float4 z = make_float4(0.f,0.f,0.f,0.f);
    if (i < NN16/4) { ((float4*)g_e)[i] = z; ((float4*)g_h)[i] = z; }
    if (i < NNODE) { g_D[i] = 0.f; g_B[i] = 0.f; }
    if (i < CIN) { g_sum[i] = 0.0; g_sum2[i] = 0.0; }
}

// ---------------- BatchNorm stats ----------------
__global__ void k_bnstats(const float* __restrict__ x) {
    __shared__ double sh[128], sh2[128];
    int b = blockIdx.x;
    const float* p = x + b*336;
    double s = 0.0, s2 = 0.0;
    for (int i = threadIdx.x; i < 336; i += 128) { double v = p[i]; s += v; s2 += v*v; }
    sh[threadIdx.x] = s; sh2[threadIdx.x] = s2; __syncthreads();
    for (int o = 64; o > 0; o >>= 1) {
        if (threadIdx.x < o) { sh[threadIdx.x] += sh[threadIdx.x+o]; sh2[threadIdx.x] += sh2[threadIdx.x+o]; }
        __syncthreads();
    }
    if (threadIdx.x == 0) {
        int c = b & 15;
        atomicAdd(&g_sum[c], sh[0]);
        atomicAdd(&g_sum2[c], sh2[0]);
    }
}

__global__ void k_bnfin(const float* __restrict__ gamma, const float* __restrict__ beta) {
    int c = threadIdx.x;
    if (c >= CIN) return;
    double cnt = (double)NB * TT * VMD;
    double mean = g_sum[c] / cnt;
    double var  = g_sum2[c] / cnt - mean*mean;
    float sc = gamma[c] * rsqrtf((float)var + 1e-5f);
    g_scale[c] = sc;
    g_shift[c] = beta[c] - (float)mean * sc;
}

// stage raw + normalized x node-major via SMEM transpose (coalesced both sides)
__global__ void k_bnx2(const float* __restrict__ x) {
    __shared__ float sx[16*337];
    const int n = blockIdx.x, tid = threadIdx.x;
    const float* xp = x + (size_t)n*5376;
    for (int i = tid; i < 5376; i += 256) {
        int c = i / 336, rem = i % 336;
        sx[c*337 + rem] = xp[i];
    }
    __syncthreads();
    const size_t base = (size_t)n*5376;
    for (int i = tid; i < 5376; i += 256) {
        int rem = i >> 4, c = i & 15;
        float v = sx[c*337 + rem];
        g_xn[base + i] = v;
        g_xb[base + i] = v * g_scale[c] + g_shift[c];
    }
}

// ---------------- hypergraph: degrees ----------------
__global__ void k_deg(const int* __restrict__ hi) {
    int i = blockIdx.x*blockDim.x + threadIdx.x;
    if (i >= EINC) return;
    atomicAdd(&g_D[hi[i]], 1.f);
    atomicAdd(&g_B[hi[EINC + i]], 1.f);
}

__global__ void k_inv() {
    int i = blockIdx.x*blockDim.x + threadIdx.x;
    if (i >= NNODE) return;
    float d = g_D[i]; g_D[i] = (d > 0.f) ? (1.f/d) : 0.f;
    float b = g_B[i]; g_B[i] = (b > 0.f) ? (1.f/b) : 0.f;
}

// pass 1: e16[edge] += xn[node]          (Binv applied in pass 2)
__global__ void k_scatter_e(const int* __restrict__ hi) {
    unsigned gi = blockIdx.x*blockDim.x + threadIdx.x;   // EINC*4
    if (gi >= (unsigned)EINC * 4u) return;
    int i = (int)(gi >> 2), g = (int)((gi & 3u) << 2);
    int node = __ldg(&hi[i]), edge = __ldg(&hi[EINC + i]);
    float4 v = *(const float4*)(g_xn + (size_t)node*16 + g);
    float* dst = g_e + (size_t)edge*16 + g;
    asm volatile("red.global.add.v4.f32 [%0], {%1, %2, %3, %4};"
                 :: "l"(dst), "f"(v.x), "f"(v.y), "f"(v.z), "f"(v.w) : "memory");
}

// pass 2: h16[node] += Binv[edge]*e16[edge]   (Dinv applied in k_seq2)
__global__ void k_scatter_h(const int* __restrict__ hi) {
    unsigned gi = blockIdx.x*blockDim.x + threadIdx.x;   // EINC*4
    if (gi >= (unsigned)EINC * 4u) return;
    int i = (int)(gi >> 2), g = (int)((gi & 3u) << 2);
    int node = __ldg(&hi[i]), edge = __ldg(&hi[EINC + i]);
    float w = g_B[edge];
    float4 v = *(const float4*)(g_e + (size_t)edge*16 + g);
    v.x *= w; v.y *= w; v.z *= w; v.w *= w;
    float* dst = g_h + (size_t)node*16 + g;
    asm volatile("red.global.add.v4.f32 [%0], {%1, %2, %3, %4};"
                 :: "l"(dst), "f"(v.x), "f"(v.y), "f"(v.z), "f"(v.w) : "memory");
}

// ---------------- fused: (Dinv * h16) @ hcw^T + hc_b  -> time-conv -> seq ----------------
// block per sample n; everything SMEM-resident
__global__ __launch_bounds__(256) void k_seq2(
        const float* __restrict__ hcw, const float* __restrict__ hcb,
        const float* __restrict__ cw,  const float* __restrict__ cb) {
    __shared__ float sh_h[336*16];   // Dinv-scaled h16, [nodeL][c_in]
    __shared__ float sh_w[16*64];    // hcw transposed: [c_in][c_out]
    __shared__ float sh_hv[336];
    __shared__ float sh_cw[64], sh_cb[8], sh_hcb[64];
    const int n = blockIdx.x, tid = threadIdx.x;
    const float* hsrc = g_h + (size_t)n*5376;
    const float* dsrc = g_D + n*336;
    for (int i = tid; i < 5376; i += 256)
        sh_h[i] = hsrc[i] * dsrc[i >> 4];
    for (int i = tid; i < 1024; i += 256) {
        int co = i & 63, ci = i >> 6;
        sh_w[ci*64 + co] = hcw[co*16 + ci];
    }
    if (tid < 64) { sh_cw[tid] = cw[tid]; sh_hcb[tid] = hcb[tid]; }
    if (tid < 8)  sh_cb[tid] = cb[tid];

    for (int w = 0; w < 8; w++) {
        __syncthreads();
        for (int inner = tid; inner < 336; inner += 256) {
            int nodeL = w*42 + (inner >> 6);
            int c = inner & 63;
            const float* hr = sh_h + nodeL*16;
            float acc = sh_hcb[c];
            #pragma unroll
            for (int j = 0; j < 16; j++) acc += hr[j] * sh_w[j*64 + c];
            sh_hv[inner] = acc;
        }
        __syncthreads();
        for (int p = tid; p < 336; p += 256) {
            int o = p / 42, vm = p % 42;
            float acc = sh_cb[o];
            #pragma unroll
            for (int t = 0; t < 8; t++) acc += sh_cw[o*8 + t] * sh_hv[t*42 + vm];
            g_seq[(size_t)(n*8 + o)*336 + w*42 + vm] = acc;
        }
    }
}

// ---------------- weight folding ----------------
__global__ void k_cw(const float* __restrict__ W1, const float* __restrict__ wq,
                     float* __restrict__ Wc) {
    int i = blockIdx.x*blockDim.x + threadIdx.x;
    if (i >= EMB*EMB) return;
    int o = i / EMB, ii = i % EMB;
    float acc = 0.f;
    for (int m = 0; m < EMB; m++) acc += W1[o*EMB + m] * wq[m*EMB + ii];
    Wc[i] = acc;
}

__global__ void k_cb(const float* __restrict__ W1, const float* __restrict__ b1,
                     const float* __restrict__ bq, float* __restrict__ bc) {
    int o = blockIdx.x*blockDim.x + threadIdx.x;
    if (o >= EMB) return;
    float acc = b1[o];
    for (int m = 0; m < EMB; m++) acc += W1[o*EMB + m] * bq[m];
    bc[o] = acc;
}

// ---------------- 128x128 f32x2 SGEMM (split 4+4 microtile, conflict-reduced) ----------------
#define ROWFMA(RR, AV) { unsigned long long aa = pack2(AV, AV); \
    acc2[RR][0] = ffma2(aa, bq0.x, acc2[RR][0]); \
    acc2[RR][1] = ffma2(aa, bq0.y, acc2[RR][1]); \
    acc2[RR][2] = ffma2(aa, bq1.x, acc2[RR][2]); \
    acc2[RR][3] = ffma2(aa, bq1.y, acc2[RR][3]); }

#define GEMM_MAIN(KDIM, LOADCOND) \
    int buf = 0; \
    _Pragma("unroll 1") \
    for (int kk = 16; kk <= (KDIM); kk += 16) { \
        if (kk < (KDIM)) { LOADCOND } \
        _Pragma("unroll") \
        for (int k = 0; k < 16; k++) { \
            float4 a0 = *(const float4*)&As[buf][k][ty<<2]; \
            float4 a1 = *(const float4*)&As[buf][k][(ty<<2)+64]; \
            ulonglong2 bq0 = *(const ulonglong2*)&Bs[buf][k][tx<<2]; \
            ulonglong2 bq1 = *(const ulonglong2*)&Bs[buf][k][(tx<<2)+64]; \
            ROWFMA(0, a0.x) ROWFMA(1, a0.y) ROWFMA(2, a0.z) ROWFMA(3, a0.w) \
            ROWFMA(4, a1.x) ROWFMA(5, a1.y) ROWFMA(6, a1.z) ROWFMA(7, a1.w) \
        } \
        if (kk < (KDIM)) { \
            int nb = buf ^ 1; \
            As[nb][lk+0][lr]=pa0.x; As[nb][lk+1][lr]=pa0.y; As[nb][lk+2][lr]=pa0.z; As[nb][lk+3][lr]=pa0.w; \
            As[nb][lk+0][lr+64]=pa1.x; As[nb][lk+1][lr+64]=pa1.y; As[nb][lk+2][lr+64]=pa1.z; As[nb][lk+3][lr+64]=pa1.w; \
            Bs[nb][lk+0][lr]=pb0.x; Bs[nb][lk+1][lr]=pb0.y; Bs[nb][lk+2][lr]=pb0.z; Bs[nb][lk+3][lr]=pb0.w; \
            Bs[nb][lk+0][lr+64]=pb1.x; Bs[nb][lk+1][lr+64]=pb1.y; Bs[nb][lk+2][lr+64]=pb1.z; Bs[nb][lk+3][lr+64]=pb1.w; \
        } \
        __syncthreads(); \
        buf ^= 1; \
    }

__global__ __launch_bounds__(256) void k_gemm128(
        const float* __restrict__ A, const float* __restrict__ B,
        const float* __restrict__ bias, float* __restrict__ C,
        int Nn, int K) {
    __shared__ __align__(16) float As[2][16][128];
    __shared__ __align__(16) float Bs[2][16][128];
    const int tid = threadIdx.x;
    const int row0 = blockIdx.y << 7, col0 = blockIdx.x << 7;
    const int lr = tid >> 2;
    const int lk = (tid & 3) << 2;
    const int tx = tid & 15, ty = tid >> 4;
    const float* Ap  = A + (size_t)(row0 + lr)*K + lk;
    const float* Ap2 = Ap + (size_t)64*K;
    const int br0 = col0 + lr, br1 = br0 + 64;
    const bool v0 = br0 < Nn, v1 = br1 < Nn;
    const float* Bp0 = B + (size_t)(v0 ? br0 : 0)*K + lk;
    const float* Bp1 = B + (size_t)(v1 ? br1 : 0)*K + lk;
    const float4 z = make_float4(0.f,0.f,0.f,0.f);
    float4 pa0 = *(const float4*)Ap;
    float4 pa1 = *(const float4*)Ap2;
    float4 pb0 = v0 ? *(const float4*)Bp0 : z;
    float4 pb1 = v1 ? *(const float4*)Bp1 : z;
    unsigned long long acc2[8][4];
    #pragma unroll
    for (int i = 0; i < 8; i++)
        #pragma unroll
        for (int j = 0; j < 4; j++) acc2[i][j] = 0ull;

    As[0][lk+0][lr]=pa0.x; As[0][lk+1][lr]=pa0.y; As[0][lk+2][lr]=pa0.z; As[0][lk+3][lr]=pa0.w;
    As[0][lk+0][lr+64]=pa1.x; As[0][lk+1][lr+64]=pa1.y; As[0][lk+2][lr+64]=pa1.z; As[0][lk+3][lr+64]=pa1.w;
    Bs[0][lk+0][lr]=pb0.x; Bs[0][lk+1][lr]=pb0.y; Bs[0][lk+2][lr]=pb0.z; Bs[0][lk+3][lr]=pb0.w;
    Bs[0][lk+0][lr+64]=pb1.x; Bs[0][lk+1][lr+64]=pb1.y; Bs[0][lk+2][lr+64]=pb1.z; Bs[0][lk+3][lr+64]=pb1.w;
    __syncthreads();

    GEMM_MAIN(K,
        pa0 = *(const float4*)(Ap + kk);
        pa1 = *(const float4*)(Ap2 + kk);
        pb0 = v0 ? *(const float4*)(Bp0 + kk) : z;
        pb1 = v1 ? *(const float4*)(Bp1 + kk) : z; )

    const int cc0 = col0 + (tx << 2);
    const int cc1 = cc0 + 64;
    #pragma unroll
    for (int i = 0; i < 8; i++) {
        int r = row0 + ((i < 4) ? ((ty<<2) + i) : (64 + (ty<<2) + i - 4));
        float2 u0 = unpack2(acc2[i][0]);
        float2 u1 = unpack2(acc2[i][1]);
        float2 u2 = unpack2(acc2[i][2]);
        float2 u3 = unpack2(acc2[i][3]);
        float o0[4] = {u0.x, u0.y, u1.x, u1.y};
        float o1[4] = {u2.x, u2.y, u3.x, u3.y};
        if (cc0 + 3 < Nn) {
            float4 w0 = make_float4(o0[0]+bias[cc0], o0[1]+bias[cc0+1],
                                    o0[2]+bias[cc0+2], o0[3]+bias[cc0+3]);
            *(float4*)(C + (size_t)r*Nn + cc0) = w0;
        } else {
            #pragma unroll
            for (int j = 0; j < 4; j++)
                if (cc0 + j < Nn) C[(size_t)r*Nn + cc0 + j] = o0[j] + bias[cc0+j];
        }
        if (cc1 + 3 < Nn) {
            float4 w1 = make_float4(o1[0]+bias[cc1], o1[1]+bias[cc1+1],
                                    o1[2]+bias[cc1+2], o1[3]+bias[cc1+3]);
            *(float4*)(C + (size_t)r*Nn + cc1) = w1;
        } else {
            #pragma unroll
            for (int j = 0; j < 4; j++)
                if (cc1 + j < Nn) C[(size_t)r*Nn + cc1 + j] = o1[j] + bias[cc1+j];
        }
    }
}

// ---------------- fc GEMM + fused residual + relu ----------------
__global__ __launch_bounds__(256) void k_gemm_fc(
        const float* __restrict__ A, const float* __restrict__ B,
        const float* __restrict__ fcb, const float* __restrict__ pw,
        const float* __restrict__ pb, float* __restrict__ C) {
    __shared__ __align__(16) float As[2][16][128];
    __shared__ __align__(16) float Bs[2][16][128];
    __shared__ __align__(16) float s_pw[16*64];
    __shared__ __align__(16) float s_pb[64];
    const int tid = threadIdx.x;
    for (int i = tid; i < 16*64; i += 256) {
        int c = i >> 6, co = i & 63;
        s_pw[i] = pw[co*16 + c];
    }
    if (tid < 64) s_pb[tid] = pb[tid];

    const int row0 = blockIdx.y << 7, col0 = blockIdx.x << 7;
    const int lr = tid >> 2;
    const int lk = (tid & 3) << 2;
    const int tx = tid & 15, ty = tid >> 4;
    const float* Ap  = A + (size_t)(row0 + lr)*336 + lk;
    const float* Ap2 = Ap + (size_t)64*336;
    const float* Bp0 = B + (size_t)(col0 + lr)*336 + lk;
    const float* Bp1 = Bp0 + (size_t)64*336;
    float4 pa0 = *(const float4*)Ap;
    float4 pa1 = *(const float4*)Ap2;
    float4 pb0 = *(const float4*)Bp0;
    float4 pb1 = *(const float4*)Bp1;
    unsigned long long acc2[8][4];
    #pragma unroll
    for (int i = 0; i < 8; i++)
        #pragma unroll
        for (int j = 0; j < 4; j++) acc2[i][j] = 0ull;

    As[0][lk+0][lr]=pa0.x; As[0][lk+1][lr]=pa0.y; As[0][lk+2][lr]=pa0.z; As[0][lk+3][lr]=pa0.w;
    As[0][lk+0][lr+64]=pa1.x; As[0][lk+1][lr+64]=pa1.y; As[0][lk+2][lr+64]=pa1.z; As[0][lk+3][lr+64]=pa1.w;
    Bs[0][lk+0][lr]=pb0.x; Bs[0][lk+1][lr]=pb0.y; Bs[0][lk+2][lr]=pb0.z; Bs[0][lk+3][lr]=pb0.w;
    Bs[0][lk+0][lr+64]=pb1.x; Bs[0][lk+1][lr+64]=pb1.y; Bs[0][lk+2][lr+64]=pb1.z; Bs[0][lk+3][lr+64]=pb1.w;
    __syncthreads();

    GEMM_MAIN(336,
        pa0 = *(const float4*)(Ap + kk);
        pa1 = *(const float4*)(Ap2 + kk);
        pb0 = *(const float4*)(Bp0 + kk);
        pb1 = *(const float4*)(Bp1 + kk); )

    // stage xb rows for residual into As (dead after main loop; sync above protects)
    float* xs = &As[0][0][0];     // xs[vml*2048 + mr*16 + c]
    const int vm0 = col0 >> 6;
    for (int t = tid; t < 4096; t += 256) {
        int vml = t >> 11, mr = (t >> 4) & 127, c = t & 15;
        xs[vml*2048 + mr*16 + c] = g_xb[((size_t)(row0 + mr)*42 + vm0 + vml)*16 + c];
    }
    __syncthreads();

    const int cb0 = tx << 2;
    const int cc0 = col0 + cb0, cc1 = cc0 + 64;
    // residual: acc += pw^T xb for both vm halves
    #pragma unroll
    for (int c = 0; c < 16; c++) {
        ulonglong2 w0 = *(const ulonglong2*)&s_pw[c*64 + cb0];
        #pragma unroll
        for (int i = 0; i < 8; i++) {
            int mr = (i < 4) ? ((ty<<2) + i) : (64 + (ty<<2) + i - 4);
            float xv0 = xs[mr*16 + c];
            float xv1 = xs[2048 + mr*16 + c];
            unsigned long long p0 = pack2(xv0, xv0);
            unsigned long long p1 = pack2(xv1, xv1);
            acc2[i][0] = ffma2(p0, w0.x, acc2[i][0]);
            acc2[i][1] = ffma2(p0, w0.y, acc2[i][1]);
            acc2[i][2] = ffma2(p1, w0.x, acc2[i][2]);
            acc2[i][3] = ffma2(p1, w0.y, acc2[i][3]);
        }
    }
    float bs0[4], bs1[4];
    #pragma unroll
    for (int j = 0; j < 4; j++) {
        bs0[j] = fcb[cc0 + j] + s_pb[cb0 + j];
        bs1[j] = fcb[cc1 + j] + s_pb[cb0 + j];
    }
    #pragma unroll
    for (int i = 0; i < 8; i++) {
        int r = row0 + ((i < 4) ? ((ty<<2) + i) : (64 + (ty<<2) + i - 4));
        float2 u0 = unpack2(acc2[i][0]);
        float2 u1 = unpack2(acc2[i][1]);
        float2 u2 = unpack2(acc2[i][2]);
        float2 u3 = unpack2(acc2[i][3]);
        float4 o0 = make_float4(fmaxf(u0.x+bs0[0],0.f), fmaxf(u0.y+bs0[1],0.f),
                                fmaxf(u1.x+bs0[2],0.f), fmaxf(u1.y+bs0[3],0.f));
        float4 o1 = make_float4(fmaxf(u2.x+bs1[0],0.f), fmaxf(u2.y+bs1[1],0.f),
                                fmaxf(u3.x+bs1[2],0.f), fmaxf(u3.y+bs1[3],0.f));
        *(float4*)(C + (size_t)r*2688 + cc0) = o0;
        *(float4*)(C + (size_t)r*2688 + cc1) = o1;
    }
}

// ---------------- attention ----------------
__global__ void k_attn() {
    __shared__ float sc[64], at[64];
    const int n = blockIdx.x, h = blockIdx.y;
    const float* Q  = g_qkv + (size_t)n*8*1008 + h*84;
    const float* Kp = Q + 336;
    const float* Vp = Q + 672;
    float*       AO = g_ao + (size_t)n*8*EMB + h*84;
    const int tid = threadIdx.x, s = tid >> 3, t = tid & 7;
    float acc = 0.f;
    #pragma unroll 4
    for (int d = 0; d < 84; d++) acc += Q[s*1008 + d] * Kp[t*1008 + d];
    sc[tid] = acc * 0.1091089451179961805f;   // 1/sqrt(84)
    __syncthreads();
    float mx = sc[s*8];
    #pragma unroll
    for (int k = 1; k < 8; k++) mx = fmaxf(mx, sc[s*8 + k]);
    float e = expf(sc[tid] - mx);
    at[tid] = e;
    __syncthreads();
    float sum = 0.f;
    #pragma unroll
    for (int k = 0; k < 8; k++) sum += at[s*8 + k];
    float a = e / sum;
    __syncthreads();
    at[tid] = a;
    __syncthreads();
    for (int idx = tid; idx < 672; idx += 64) {
        int ss = idx / 84, d = idx - ss*84;
        float o = 0.f;
        #pragma unroll
        for (int k = 0; k < 8; k++) o += at[ss*8 + k] * Vp[k*1008 + d];
        AO[ss*EMB + d] = o;
    }
}

// ---------------- launcher ----------------
extern "C" void kernel_launch(void* const* d_in, const int* in_sizes, int n_in,
                              void* d_out, int out_size) {
    const float* x   = (const float*)d_in[0];
    const int*   hi  = (const int*)  d_in[1];
    const float* hcw = (const float*)d_in[2];
    const float* hcb = (const float*)d_in[3];
    const float* cw  = (const float*)d_in[4];
    const float* cb  = (const float*)d_in[5];
    const float* gam = (const float*)d_in[6];
    const float* bet = (const float*)d_in[7];
    const float* pw  = (const float*)d_in[8];
    const float* pb  = (const float*)d_in[9];
    const float* wq  = (const float*)d_in[10];
    const float* bq  = (const float*)d_in[11];
    const float* wk  = (const float*)d_in[12];
    const float* bk  = (const float*)d_in[13];
    const float* wv  = (const float*)d_in[14];
    const float* bv  = (const float*)d_in[15];
    const float* ipw = (const float*)d_in[16];
    const float* ipb = (const float*)d_in[17];
    const float* opw = (const float*)d_in[18];
    const float* opb = (const float*)d_in[19];
    const float* fw  = (const float*)d_in[20];
    const float* fb  = (const float*)d_in[21];
    float* out = (float*)d_out;

    float *p_seq, *p_qkv, *p_ao, *p_o2, *p_Wc, *p_bc;
    cudaGetSymbolAddress((void**)&p_seq, g_seq);
    cudaGetSymbolAddress((void**)&p_qkv, g_qkv);
    cudaGetSymbolAddress((void**)&p_ao,  g_ao);
    cudaGetSymbolAddress((void**)&p_o2,  g_o2);
    cudaGetSymbolAddress((void**)&p_Wc,  g_Wc);
    cudaGetSymbolAddress((void**)&p_bc,  g_bc);

    k_zero<<<(NN16/4 + 255)/256, 256>>>();
    k_bnstats<<<NB*CIN, 128>>>(x);
    k_bnfin<<<1, 32>>>(gam, bet);
    k_bnx2<<<NB, 256>>>(x);
    k_deg<<<(EINC + 255)/256, 256>>>(hi);
    k_inv<<<(NNODE + 255)/256, 256>>>();
    {
        long long tot = (long long)EINC * 4;
        int blocks = (int)((tot + 255) / 256);
        k_scatter_e<<<blocks, 256>>>(hi);
        k_scatter_h<<<blocks, 256>>>(hi);
    }
    k_seq2<<<NB, 256>>>(hcw, hcb, cw, cb);
    k_cw<<<(EMB*EMB + 255)/256, 256>>>(ipw,             wq, p_Wc);
    k_cw<<<(EMB*EMB + 255)/256, 256>>>(ipw +   EMB*EMB, wk, p_Wc +   EMB*EMB);
    k_cw<<<(EMB*EMB + 255)/256, 256>>>(ipw + 2*EMB*EMB, wv, p_Wc + 2*EMB*EMB);
    k_cb<<<2, 256>>>(ipw,             ipb,         bq, p_bc);
    k_cb<<<2, 256>>>(ipw +   EMB*EMB, ipb +   EMB, bk, p_bc + EMB);
    k_cb<<<2, 256>>>(ipw + 2*EMB*EMB, ipb + 2*EMB, bv, p_bc + 2*EMB);

    dim3 gqkv(8, ROWS/128);
    k_gemm128<<<gqkv, 256>>>(p_seq, p_Wc, p_bc, p_qkv, 3*EMB, EMB);
    k_attn<<<dim3(NB, 4), 64>>>();
    dim3 gop(3, ROWS/128);
    k_gemm128<<<gop, 256>>>(p_ao, opw, opb, p_o2, EMB, EMB);
    dim3 gfc(OUTW/128, ROWS/128);
    k_gemm_fc<<<gfc, 256>>>(p_o2, fw, fb, pw, pb, out);
}

// round 5
// speedup vs baseline: 3.7176x; 1.3479x over previous
#include <cuda_runtime.h>
#include <cuda_bf16.h>
#include <math.h>

#define NB    2048
#define CIN   16
#define VMD   42
#define NNODE (NB*8*VMD)            // 688128
#define EINC  (4*NNODE)             // 2752512
#define EMB   336
#define ROWS  (NB*8)                // 16384
#define KDIM  336
#define NSTEP 21
#define NN16  (NNODE*16)

// ---------------- scratch ----------------
__device__ __align__(16) float  g_xn[NN16];
__device__ __align__(16) float  g_xb[NN16];
__device__ __align__(16) float  g_e [NN16];
__device__ __align__(16) float  g_h [NN16];
__device__ __align__(16) float  g_D [NNODE];
__device__ __align__(16) float  g_B [NNODE];
__device__ __align__(16) float  g_seq[ROWS*EMB];
__device__ __align__(16) float  g_qkv[ROWS*3*EMB];
__device__ __align__(16) float  g_ao [ROWS*EMB];
__device__ __align__(16) float  g_o2 [ROWS*EMB];
__device__ __align__(16) float  g_Wc [3*EMB*EMB];
__device__ __align__(16) float  g_bc [3*EMB];
__device__ double g_sum[CIN], g_sum2[CIN];
__device__ float  g_scale[CIN], g_shift[CIN];
// bf16 hi/lo staging (K=336 exactly; B-row counts padded to /128)
__device__ __align__(16) __nv_bfloat16 g_seqh[ROWS*KDIM], g_seql[ROWS*KDIM];
__device__ __align__(16) __nv_bfloat16 g_aoh [ROWS*KDIM], g_aol [ROWS*KDIM];
__device__ __align__(16) __nv_bfloat16 g_o2h [ROWS*KDIM], g_o2l [ROWS*KDIM];
__device__ __align__(16) __nv_bfloat16 g_wch [1024*KDIM], g_wcl [1024*KDIM];
__device__ __align__(16) __nv_bfloat16 g_oph [384*KDIM],  g_opl [384*KDIM];
__device__ __align__(16) __nv_bfloat16 g_fwh [2688*KDIM], g_fwl [2688*KDIM];

// ---------------- helpers ----------------
__device__ __forceinline__ unsigned smem_u32(const void* p) {
    unsigned a;
    asm("{ .reg .u64 t; cvta.to.shared.u64 t, %1; cvt.u32.u64 %0, t; }" : "=r"(a) : "l"(p));
    return a;
}
__device__ __forceinline__ void ldm4(unsigned* r, unsigned addr) {
    asm volatile("ldmatrix.sync.aligned.m8n8.x4.shared.b16 {%0,%1,%2,%3}, [%4];"
        : "=r"(r[0]), "=r"(r[1]), "=r"(r[2]), "=r"(r[3]) : "r"(addr));
}
__device__ __forceinline__ void mma16816(float* d, const unsigned* a, const unsigned* b) {
    asm volatile("mma.sync.aligned.m16n8k16.row.col.f32.bf16.bf16.f32 "
        "{%0,%1,%2,%3}, {%4,%5,%6,%7}, {%8,%9}, {%0,%1,%2,%3};"
        : "+f"(d[0]), "+f"(d[1]), "+f"(d[2]), "+f"(d[3])
        : "r"(a[0]), "r"(a[1]), "r"(a[2]), "r"(a[3]), "r"(b[0]), "r"(b[1]));
}
__device__ __forceinline__ unsigned long long ffma2(unsigned long long a,
                                                    unsigned long long b,
                                                    unsigned long long c) {
    unsigned long long d;
    asm("fma.rn.f32x2 %0, %1, %2, %3;" : "=l"(d) : "l"(a), "l"(b), "l"(c));
    return d;
}
__device__ __forceinline__ unsigned long long pack2(float x, float y) {
    unsigned long long d;
    asm("mov.b64 %0, {%1, %2};" : "=l"(d) : "f"(x), "f"(y));
    return d;
}
__device__ __forceinline__ float2 unpack2(unsigned long long v) {
    float2 r;
    asm("mov.b64 {%0, %1}, %2;" : "=f"(r.x), "=f"(r.y) : "l"(v));
    return r;
}

// ---------------- init ----------------
__global__ void k_zero() {
    int i = blockIdx.x*blockDim.x + threadIdx.x;
    float4 z = make_float4(0.f,0.f,0.f,0.f);
    if (i < NN16/4) { ((float4*)g_e)[i] = z; ((float4*)g_h)[i] = z; }
    if (i < NNODE) { g_D[i] = 0.f; g_B[i] = 0.f; }
    if (i < CIN) { g_sum[i] = 0.0; g_sum2[i] = 0.0; }
}

// ---------------- BatchNorm ----------------
__global__ void k_bnstats(const float* __restrict__ x) {
    __shared__ double sh[128], sh2[128];
    int b = blockIdx.x;
    const float* p = x + b*336;
    double s = 0.0, s2 = 0.0;
    for (int i = threadIdx.x; i < 336; i += 128) { double v = p[i]; s += v; s2 += v*v; }
    sh[threadIdx.x] = s; sh2[threadIdx.x] = s2; __syncthreads();
    for (int o = 64; o > 0; o >>= 1) {
        if (threadIdx.x < o) { sh[threadIdx.x] += sh[threadIdx.x+o]; sh2[threadIdx.x] += sh2[threadIdx.x+o]; }
        __syncthreads();
    }
    if (threadIdx.x == 0) {
        int c = b & 15;
        atomicAdd(&g_sum[c], sh[0]);
        atomicAdd(&g_sum2[c], sh2[0]);
    }
}

__global__ void k_bnfin(const float* __restrict__ gamma, const float* __restrict__ beta) {
    int c = threadIdx.x;
    if (c >= CIN) return;
    double cnt = (double)NNODE;
    double mean = g_sum[c] / cnt;
    double var  = g_sum2[c] / cnt - mean*mean;
    float sc = gamma[c] * rsqrtf((float)var + 1e-5f);
    g_scale[c] = sc;
    g_shift[c] = beta[c] - (float)mean * sc;
}

__global__ void k_bnx2(const float* __restrict__ x) {
    __shared__ float sx[16*337];
    const int n = blockIdx.x, tid = threadIdx.x;
    const float* xp = x + (size_t)n*5376;
    for (int i = tid; i < 5376; i += 256) {
        int c = i / 336, rem = i % 336;
        sx[c*337 + rem] = xp[i];
    }
    __syncthreads();
    const size_t base = (size_t)n*5376;
    for (int i = tid; i < 5376; i += 256) {
        int rem = i >> 4, c = i & 15;
        float v = sx[c*337 + rem];
        g_xn[base + i] = v;
        g_xb[base + i] = v * g_scale[c] + g_shift[c];
    }
}

// ---------------- hypergraph ----------------
__global__ void k_deg(const int* __restrict__ hi) {
    int i = blockIdx.x*blockDim.x + threadIdx.x;
    if (i >= EINC) return;
    atomicAdd(&g_D[hi[i]], 1.f);
    atomicAdd(&g_B[hi[EINC + i]], 1.f);
}

__global__ void k_inv() {
    int i = blockIdx.x*blockDim.x + threadIdx.x;
    if (i >= NNODE) return;
    float d = g_D[i]; g_D[i] = (d > 0.f) ? (1.f/d) : 0.f;
    float b = g_B[i]; g_B[i] = (b > 0.f) ? (1.f/b) : 0.f;
}

__global__ void k_scatter_e(const int* __restrict__ hi) {
    unsigned gi = blockIdx.x*blockDim.x + threadIdx.x;
    if (gi >= (unsigned)EINC * 4u) return;
    int i = (int)(gi >> 2), g = (int)((gi & 3u) << 2);
    int node = __ldg(&hi[i]), edge = __ldg(&hi[EINC + i]);
    float4 v = *(const float4*)(g_xn + (size_t)node*16 + g);
    float* dst = g_e + (size_t)edge*16 + g;
    asm volatile("red.global.add.v4.f32 [%0], {%1, %2, %3, %4};"
                 :: "l"(dst), "f"(v.x), "f"(v.y), "f"(v.z), "f"(v.w) : "memory");
}

__global__ void k_scatter_h(const int* __restrict__ hi) {
    unsigned gi = blockIdx.x*blockDim.x + threadIdx.x;
    if (gi >= (unsigned)EINC * 4u) return;
    int i = (int)(gi >> 2), g = (int)((gi & 3u) << 2);
    int node = __ldg(&hi[i]), edge = __ldg(&hi[EINC + i]);
    float w = g_B[edge];
    float4 v = *(const float4*)(g_e + (size_t)edge*16 + g);
    v.x *= w; v.y *= w; v.z *= w; v.w *= w;
    float* dst = g_h + (size_t)node*16 + g;
    asm volatile("red.global.add.v4.f32 [%0], {%1, %2, %3, %4};"
                 :: "l"(dst), "f"(v.x), "f"(v.y), "f"(v.z), "f"(v.w) : "memory");
}

// ---------------- fused hconv + time-conv -> seq ----------------
__global__ __launch_bounds__(256) void k_seq2(
        const float* __restrict__ hcw, const float* __restrict__ hcb,
        const float* __restrict__ cw,  const float* __restrict__ cb) {
    __shared__ float sh_h[336*16];
    __shared__ float sh_w[16*64];
    __shared__ float sh_hv[336];
    __shared__ float sh_cw[64], sh_cb[8], sh_hcb[64];
    const int n = blockIdx.x, tid = threadIdx.x;
    const float* hsrc = g_h + (size_t)n*5376;
    const float* dsrc = g_D + n*336;
    for (int i = tid; i < 5376; i += 256)
        sh_h[i] = hsrc[i] * dsrc[i >> 4];
    for (int i = tid; i < 1024; i += 256) {
        int co = i & 63, ci = i >> 6;
        sh_w[ci*64 + co] = hcw[co*16 + ci];
    }
    if (tid < 64) { sh_cw[tid] = cw[tid]; sh_hcb[tid] = hcb[tid]; }
    if (tid < 8)  sh_cb[tid] = cb[tid];

    for (int w = 0; w < 8; w++) {
        __syncthreads();
        for (int inner = tid; inner < 336; inner += 256) {
            int nodeL = w*42 + (inner >> 6);
            int c = inner & 63;
            const float* hr = sh_h + nodeL*16;
            float acc = sh_hcb[c];
            #pragma unroll
            for (int j = 0; j < 16; j++) acc += hr[j] * sh_w[j*64 + c];
            sh_hv[inner] = acc;
        }
        __syncthreads();
        for (int p = tid; p < 336; p += 256) {
            int o = p / 42, vm = p % 42;
            float acc = sh_cb[o];
            #pragma unroll
            for (int t = 0; t < 8; t++) acc += sh_cw[o*8 + t] * sh_hv[t*42 + vm];
            g_seq[(size_t)(n*8 + o)*336 + w*42 + vm] = acc;
        }
    }
}

// ---------------- weight folding ----------------
__global__ void k_cw(const float* __restrict__ W1, const float* __restrict__ wq,
                     float* __restrict__ Wc) {
    int i = blockIdx.x*blockDim.x + threadIdx.x;
    if (i >= EMB*EMB) return;
    int o = i / EMB, ii = i % EMB;
    float acc = 0.f;
    for (int m = 0; m < EMB; m++) acc += W1[o*EMB + m] * wq[m*EMB + ii];
    Wc[i] = acc;
}

__global__ void k_cb(const float* __restrict__ W1, const float* __restrict__ b1,
                     const float* __restrict__ bq, float* __restrict__ bc) {
    int o = blockIdx.x*blockDim.x + threadIdx.x;
    if (o >= EMB) return;
    float acc = b1[o];
    for (int m = 0; m < EMB; m++) acc += W1[o*EMB + m] * bq[m];
    bc[o] = acc;
}

// ---------------- fp32 -> bf16 hi/lo ----------------
__global__ void k_prep(const float* __restrict__ src,
                       __nv_bfloat16* __restrict__ hi, __nv_bfloat16* __restrict__ lo,
                       int total_rows, int rows_src) {
    int i = blockIdx.x*blockDim.x + threadIdx.x;
    if (i >= total_rows*KDIM) return;
    int r = i / KDIM;
    float v = (r < rows_src) ? src[i] : 0.f;
    __nv_bfloat16 h = __float2bfloat16(v);
    hi[i] = h;
    lo[i] = __float2bfloat16(v - __bfloat162float(h));
}

// ---------------- mma.sync bf16 hi/lo GEMM: C[m][n] = A[m][:]·B[n][:] + bias[n] ----------------
// 128x128 tile, 256 threads (8 warps: warpM = wid&1 -> 64 rows, warpN = wid>>1 -> 32 cols)
// SMEM: 4 staging arrays [2][128][24] bf16 (48B row stride: conflict-free ldmatrix)
#define SM_ARR   6144                      // bytes per array (2 bufs x 128 x 48B)... per buf 6144; total/array 12288
#define SMEM_DYN (49152 + 4096 + 256)

template<int FC>
__global__ __launch_bounds__(256) void k_gemm_mma(
        const __nv_bfloat16* __restrict__ Ah, const __nv_bfloat16* __restrict__ Al,
        const __nv_bfloat16* __restrict__ Bh, const __nv_bfloat16* __restrict__ Bl,
        const float* __restrict__ bias, float* __restrict__ C, int Nn,
        const float* __restrict__ pw, const float* __restrict__ pb) {
    extern __shared__ __align__(16) char dsm[];
    char* sAh = dsm;                 // [2][128][24] bf16 = 12288 B
    char* sAl = dsm + 12288;
    char* sBh = dsm + 24576;
    char* sBl = dsm + 36864;
    float* s_pw = (float*)(dsm + 49152);   // [16][64]
    float* s_pb = s_pw + 1024;             // [64]

    const int tid = threadIdx.x, lane = tid & 31, wid = tid >> 5;
    const int warpM = wid & 1, warpN = wid >> 1;
    const int row0 = blockIdx.y << 7, col0 = blockIdx.x << 7;

    if (FC) {
        for (int i = tid; i < 1024; i += 256) {
            int c = i >> 6, co = i & 63;
            s_pw[i] = pw[co*16 + c];
        }
        if (tid < 64) s_pb[tid] = pb[tid];
    }

    // global load mapping: thread -> (row = tid>>1, half = tid&1)
    const int lrow = tid >> 1, lhalf = tid & 1;
    const __nv_bfloat16* gAh = Ah + (size_t)(row0 + lrow)*KDIM + lhalf*8;
    const __nv_bfloat16* gAl = Al + (size_t)(row0 + lrow)*KDIM + lhalf*8;
    const __nv_bfloat16* gBh = Bh + (size_t)(col0 + lrow)*KDIM + lhalf*8;
    const __nv_bfloat16* gBl = Bl + (size_t)(col0 + lrow)*KDIM + lhalf*8;
    const int so = lrow*48 + lhalf*16;     // byte offset within a buffer

    // ldmatrix address bases (bytes)
    const unsigned uAh = smem_u32(sAh), uAl = smem_u32(sAl);
    const unsigned uBh = smem_u32(sBh), uBl = smem_u32(sBl);
    const int rsubA = (lane & 7) + ((lane >> 3) & 1)*8;
    const int cA = (warpM*64 + rsubA)*48 + ((lane >> 4) & 1)*16;
    const int rsubB = (lane & 7) + ((lane >> 4) & 1)*8;
    const int cB = (warpN*32 + rsubB)*48 + ((lane >> 3) & 1)*16;

    float acc[4][4][4];
    #pragma unroll
    for (int i = 0; i < 4; i++)
        #pragma unroll
        for (int j = 0; j < 4; j++)
            #pragma unroll
            for (int q = 0; q < 4; q++) acc[i][j][q] = 0.f;

    uint4 va = *(const uint4*)gAh;
    uint4 vb = *(const uint4*)gAl;
    uint4 vc = *(const uint4*)gBh;
    uint4 vd = *(const uint4*)gBl;
    *(uint4*)(sAh + so) = va;
    *(uint4*)(sAl + so) = vb;
    *(uint4*)(sBh + so) = vc;
    *(uint4*)(sBl + so) = vd;
    __syncthreads();

    #pragma unroll 1
    for (int ch = 0; ch < NSTEP; ch++) {
        if (ch + 1 < NSTEP) {
            va = *(const uint4*)(gAh + (ch+1)*16);
            vb = *(const uint4*)(gAl + (ch+1)*16);
            vc = *(const uint4*)(gBh + (ch+1)*16);
            vd = *(const uint4*)(gBl + (ch+1)*16);
        }
        {
            const unsigned bo = (unsigned)((ch & 1) * 6144);
            unsigned AH[4][4], AL[4][4];
            #pragma unroll
            for (int mt = 0; mt < 4; mt++) {
                ldm4(AH[mt], uAh + bo + cA + mt*768);
                ldm4(AL[mt], uAl + bo + cA + mt*768);
            }
            #pragma unroll
            for (int p = 0; p < 2; p++) {
                unsigned BH[4], BL[4];
                ldm4(BH, uBh + bo + cB + p*768);
                ldm4(BL, uBl + bo + cB + p*768);
                #pragma unroll
                for (int mt = 0; mt < 4; mt++) {
                    #pragma unroll
                    for (int q = 0; q < 2; q++) {
                        float* ac = acc[mt][2*p + q];
                        mma16816(ac, AH[mt], BH + 2*q);
                        mma16816(ac, AH[mt], BL + 2*q);
                        mma16816(ac, AL[mt], BH + 2*q);
                    }
                }
            }
        }
        if (ch + 1 < NSTEP) {
            __syncthreads();
            const int nb = ((ch+1) & 1) * 6144;
            *(uint4*)(sAh + nb + so) = va;
            *(uint4*)(sAl + nb + so) = vb;
            *(uint4*)(sBh + nb + so) = vc;
            *(uint4*)(sBl + nb + so) = vd;
            __syncthreads();
        }
    }

    if (!FC) {
        #pragma unroll
        for (int mt = 0; mt < 4; mt++) {
            int r1 = row0 + warpM*64 + mt*16 + (lane >> 2);
            #pragma unroll
            for (int nt = 0; nt < 4; nt++) {
                int gc = col0 + warpN*32 + nt*8 + (lane & 3)*2;
                if (gc < Nn) {
                    float b0 = __ldg(bias + gc), b1 = __ldg(bias + gc + 1);
                    float* ac = acc[mt][nt];
                    float2 o0 = make_float2(ac[0] + b0, ac[1] + b1);
                    float2 o1 = make_float2(ac[2] + b0, ac[3] + b1);
                    *(float2*)(C + (size_t)r1*Nn + gc)       = o0;
                    *(float2*)(C + (size_t)(r1 + 8)*Nn + gc) = o1;
                }
            }
        }
    } else {
        // stage xb tile: xs[vml][128][17] floats (stride 17 kills LDS conflicts)
        __syncthreads();
        float* xs = (float*)dsm;            // 2*128*17*4 = 17408 B < 49152
        const int v0 = col0 >> 6;
        for (int i = tid; i < 4096; i += 256) {
            int vml = i >> 11, r = (i >> 4) & 127, c = i & 15;
            xs[vml*2176 + r*17 + c] = g_xb[((size_t)(row0 + r)*42 + v0 + vml)*16 + c];
        }
        __syncthreads();

        const int vml = warpN >> 1;
        #pragma unroll
        for (int mt = 0; mt < 4; mt++) {
            int rl1 = warpM*64 + mt*16 + (lane >> 2);
            int rl2 = rl1 + 8;
            float xa[16], xc2[16];
            #pragma unroll
            for (int c = 0; c < 16; c++) {
                xa[c]  = xs[vml*2176 + rl1*17 + c];
                xc2[c] = xs[vml*2176 + rl2*17 + c];
            }
            #pragma unroll
            for (int nt = 0; nt < 4; nt++) {
                int co = (warpN & 1)*32 + nt*8 + (lane & 3)*2;
                int gc = col0 + (warpN & 1)*32 + (vml ? 64 : 0) + nt*8 + (lane & 3)*2;
                float fb0 = __ldg(bias + gc) + s_pb[co];
                float fb1 = __ldg(bias + gc + 1) + s_pb[co + 1];
                unsigned long long rv1 = pack2(fb0, fb1);
                unsigned long long rv2 = rv1;
                #pragma unroll
                for (int c = 0; c < 16; c++) {
                    unsigned long long w2 = *(const unsigned long long*)&s_pw[c*64 + co];
                    rv1 = ffma2(pack2(xa[c],  xa[c]),  w2, rv1);
                    rv2 = ffma2(pack2(xc2[c], xc2[c]), w2, rv2);
                }
                float2 u1 = unpack2(rv1), u2 = unpack2(rv2);
                float* ac = acc[mt][nt];
                int r1 = row0 + rl1, r2 = row0 + rl2;
                float2 o0 = make_float2(fmaxf(ac[0] + u1.x, 0.f), fmaxf(ac[1] + u1.y, 0.f));
                float2 o1 = make_float2(fmaxf(ac[2] + u2.x, 0.f), fmaxf(ac[3] + u2.y, 0.f));
                *(float2*)(C + (size_t)r1*2688 + gc) = o0;
                *(float2*)(C + (size_t)r2*2688 + gc) = o1;
            }
        }
    }
}

// ---------------- attention ----------------
__global__ void k_attn() {
    __shared__ float sc[64], at[64];
    const int n = blockIdx.x, h = blockIdx.y;
    const float* Q  = g_qkv + (size_t)n*8*1008 + h*84;
    const float* Kp = Q + 336;
    const float* Vp = Q + 672;
    float*       AO = g_ao + (size_t)n*8*EMB + h*84;
    const int tid = threadIdx.x, s = tid >> 3, t = tid & 7;
    float acc = 0.f;
    #pragma unroll 4
    for (int d = 0; d < 84; d++) acc += Q[s*1008 + d] * Kp[t*1008 + d];
    sc[tid] = acc * 0.1091089451179961805f;
    __syncthreads();
    float mx = sc[s*8];
    #pragma unroll
    for (int k = 1; k < 8; k++) mx = fmaxf(mx, sc[s*8 + k]);
    float e = expf(sc[tid] - mx);
    at[tid] = e;
    __syncthreads();
    float sum = 0.f;
    #pragma unroll
    for (int k = 0; k < 8; k++) sum += at[s*8 + k];
    float a = e / sum;
    __syncthreads();
    at[tid] = a;
    __syncthreads();
    for (int idx = tid; idx < 672; idx += 64) {
        int ss = idx / 84, d = idx - ss*84;
        float o = 0.f;
        #pragma unroll
        for (int k = 0; k < 8; k++) o += at[ss*8 + k] * Vp[k*1008 + d];
        AO[ss*EMB + d] = o;
    }
}

// ---------------- launcher ----------------
extern "C" void kernel_launch(void* const* d_in, const int* in_sizes, int n_in,
                              void* d_out, int out_size) {
    const float* x   = (const float*)d_in[0];
    const int*   hi  = (const int*)  d_in[1];
    const float* hcw = (const float*)d_in[2];
    const float* hcb = (const float*)d_in[3];
    const float* cw  = (const float*)d_in[4];
    const float* cb  = (const float*)d_in[5];
    const float* gam = (const float*)d_in[6];
    const float* bet = (const float*)d_in[7];
    const float* pw  = (const float*)d_in[8];
    const float* pb  = (const float*)d_in[9];
    const float* wq  = (const float*)d_in[10];
    const float* bq  = (const float*)d_in[11];
    const float* wk  = (const float*)d_in[12];
    const float* bk  = (const float*)d_in[13];
    const float* wv  = (const float*)d_in[14];
    const float* bv  = (const float*)d_in[15];
    const float* ipw = (const float*)d_in[16];
    const float* ipb = (const float*)d_in[17];
    const float* opw = (const float*)d_in[18];
    const float* opb = (const float*)d_in[19];
    const float* fw  = (const float*)d_in[20];
    const float* fb  = (const float*)d_in[21];
    float* out = (float*)d_out;

    float *p_seq, *p_qkv, *p_ao, *p_o2, *p_Wc, *p_bc;
    cudaGetSymbolAddress((void**)&p_seq, g_seq);
    cudaGetSymbolAddress((void**)&p_qkv, g_qkv);
    cudaGetSymbolAddress((void**)&p_ao,  g_ao);
    cudaGetSymbolAddress((void**)&p_o2,  g_o2);
    cudaGetSymbolAddress((void**)&p_Wc,  g_Wc);
    cudaGetSymbolAddress((void**)&p_bc,  g_bc);
    __nv_bfloat16 *p_seqh,*p_seql,*p_aoh,*p_aol,*p_o2h,*p_o2l,*p_wch,*p_wcl,*p_oph,*p_opl,*p_fwh,*p_fwl;
    cudaGetSymbolAddress((void**)&p_seqh, g_seqh); cudaGetSymbolAddress((void**)&p_seql, g_seql);
    cudaGetSymbolAddress((void**)&p_aoh,  g_aoh);  cudaGetSymbolAddress((void**)&p_aol,  g_aol);
    cudaGetSymbolAddress((void**)&p_o2h,  g_o2h);  cudaGetSymbolAddress((void**)&p_o2l,  g_o2l);
    cudaGetSymbolAddress((void**)&p_wch,  g_wch);  cudaGetSymbolAddress((void**)&p_wcl,  g_wcl);
    cudaGetSymbolAddress((void**)&p_oph,  g_oph);  cudaGetSymbolAddress((void**)&p_opl,  g_opl);
    cudaGetSymbolAddress((void**)&p_fwh,  g_fwh);  cudaGetSymbolAddress((void**)&p_fwl,  g_fwl);

    cudaFuncSetAttribute(k_gemm_mma<0>, cudaFuncAttributeMaxDynamicSharedMemorySize, SMEM_DYN);
    cudaFuncSetAttribute(k_gemm_mma<1>, cudaFuncAttributeMaxDynamicSharedMemorySize, SMEM_DYN);

    // graph path
    k_zero<<<(NN16/4 + 255)/256, 256>>>();
    k_bnstats<<<NB*CIN, 128>>>(x);
    k_bnfin<<<1, 32>>>(gam, bet);
    k_bnx2<<<NB, 256>>>(x);
    k_deg<<<(EINC + 255)/256, 256>>>(hi);
    k_inv<<<(NNODE + 255)/256, 256>>>();
    {
        long long tot = (long long)EINC * 4;
        int blocks = (int)((tot + 255) / 256);
        k_scatter_e<<<blocks, 256>>>(hi);
        k_scatter_h<<<blocks, 256>>>(hi);
    }
    k_seq2<<<NB, 256>>>(hcw, hcb, cw, cb);

    // weight folding + bf16 prep
    k_cw<<<(EMB*EMB + 255)/256, 256>>>(ipw,             wq, p_Wc);
    k_cw<<<(EMB*EMB + 255)/256, 256>>>(ipw +   EMB*EMB, wk, p_Wc +   EMB*EMB);
    k_cw<<<(EMB*EMB + 255)/256, 256>>>(ipw + 2*EMB*EMB, wv, p_Wc + 2*EMB*EMB);
    k_cb<<<2, 256>>>(ipw,             ipb,         bq, p_bc);
    k_cb<<<2, 256>>>(ipw +   EMB*EMB, ipb +   EMB, bk, p_bc + EMB);
    k_cb<<<2, 256>>>(ipw + 2*EMB*EMB, ipb + 2*EMB, bv, p_bc + 2*EMB);
    k_prep<<<(1024*KDIM + 255)/256, 256>>>(p_Wc, p_wch, p_wcl, 1024, 1008);
    k_prep<<<(384*KDIM + 255)/256, 256>>>(opw, p_oph, p_opl, 384, 336);
    k_prep<<<(2688*KDIM + 255)/256, 256>>>(fw, p_fwh, p_fwl, 2688, 2688);
    k_prep<<<(ROWS*KDIM + 255)/256, 256>>>(p_seq, p_seqh, p_seql, ROWS, ROWS);

    // qkv: N=1008 (8 col tiles)
    k_gemm_mma<0><<<dim3(8, ROWS/128), 256, SMEM_DYN>>>(
        p_seqh, p_seql, p_wch, p_wcl, p_bc, p_qkv, 1008, nullptr, nullptr);
    k_attn<<<dim3(NB, 4), 64>>>();
    k_prep<<<(ROWS*KDIM + 255)/256, 256>>>(p_ao, p_aoh, p_aol, ROWS, ROWS);
    // out_proj: N=336 (3 col tiles)
    k_gemm_mma<0><<<dim3(3, ROWS/128), 256, SMEM_DYN>>>(
        p_aoh, p_aol, p_oph, p_opl, opb, p_o2, 336, nullptr, nullptr);
    k_prep<<<(ROWS*KDIM + 255)/256, 256>>>(p_o2, p_o2h, p_o2l, ROWS, ROWS);
    // fc: N=2688 + fused residual + relu
    k_gemm_mma<1><<<dim3(21, ROWS/128), 256, SMEM_DYN>>>(
        p_o2h, p_o2l, p_fwh, p_fwl, fb, out, 2688, pw, pb);
}

// round 6
// speedup vs baseline: 3.7671x; 1.0133x over previous
#include <cuda_runtime.h>
#include <cuda_bf16.h>
#include <math.h>

#define NB    2048
#define CIN   16
#define VMD   42
#define NNODE (NB*8*VMD)            // 688128
#define EINC  (4*NNODE)             // 2752512
#define EMB   336
#define ROWS  (NB*8)                // 16384
#define KDIM  336
#define NSTEP 21
#define NN16  (NNODE*16)

// ---------------- scratch ----------------
__device__ __align__(16) float  g_xn[NN16];
__device__ __align__(16) float  g_xb[NN16];
__device__ __align__(16) float  g_e [NN16];
__device__ __align__(16) float  g_h [NN16];
__device__ __align__(16) float  g_D [NNODE];
__device__ __align__(16) float  g_B [NNODE];
__device__ __align__(16) float  g_qkv[ROWS*3*EMB];
__device__ __align__(16) float  g_Wc [3*EMB*EMB];
__device__ __align__(16) float  g_bc [3*EMB];
__device__ double g_sum[CIN], g_sum2[CIN];
__device__ float  g_scale[CIN], g_shift[CIN];
// bf16 hi/lo staging
__device__ __align__(16) __nv_bfloat16 g_seqh[ROWS*KDIM], g_seql[ROWS*KDIM];
__device__ __align__(16) __nv_bfloat16 g_aoh [ROWS*KDIM], g_aol [ROWS*KDIM];
__device__ __align__(16) __nv_bfloat16 g_o2h [ROWS*KDIM], g_o2l [ROWS*KDIM];
__device__ __align__(16) __nv_bfloat16 g_wch [1024*KDIM], g_wcl [1024*KDIM];
__device__ __align__(16) __nv_bfloat16 g_oph [384*KDIM],  g_opl [384*KDIM];
__device__ __align__(16) __nv_bfloat16 g_fwh [2688*KDIM], g_fwl [2688*KDIM];

// ---------------- helpers ----------------
__device__ __forceinline__ unsigned smem_u32(const void* p) {
    unsigned a;
    asm("{ .reg .u64 t; cvta.to.shared.u64 t, %1; cvt.u32.u64 %0, t; }" : "=r"(a) : "l"(p));
    return a;
}
__device__ __forceinline__ void ldm4(unsigned* r, unsigned addr) {
    asm volatile("ldmatrix.sync.aligned.m8n8.x4.shared.b16 {%0,%1,%2,%3}, [%4];"
        : "=r"(r[0]), "=r"(r[1]), "=r"(r[2]), "=r"(r[3]) : "r"(addr));
}
__device__ __forceinline__ void mma16816(float* d, const unsigned* a, const unsigned* b) {
    asm volatile("mma.sync.aligned.m16n8k16.row.col.f32.bf16.bf16.f32 "
        "{%0,%1,%2,%3}, {%4,%5,%6,%7}, {%8,%9}, {%0,%1,%2,%3};"
        : "+f"(d[0]), "+f"(d[1]), "+f"(d[2]), "+f"(d[3])
        : "r"(a[0]), "r"(a[1]), "r"(a[2]), "r"(a[3]), "r"(b[0]), "r"(b[1]));
}
__device__ __forceinline__ void cpa16(unsigned dst, const void* src) {
    asm volatile("cp.async.cg.shared.global [%0], [%1], 16;" :: "r"(dst), "l"(src));
}
__device__ __forceinline__ unsigned long long ffma2(unsigned long long a,
                                                    unsigned long long b,
                                                    unsigned long long c) {
    unsigned long long d;
    asm("fma.rn.f32x2 %0, %1, %2, %3;" : "=l"(d) : "l"(a), "l"(b), "l"(c));
    return d;
}
__device__ __forceinline__ unsigned long long pack2(float x, float y) {
    unsigned long long d;
    asm("mov.b64 %0, {%1, %2};" : "=l"(d) : "f"(x), "f"(y));
    return d;
}
__device__ __forceinline__ float2 unpack2(unsigned long long v) {
    float2 r;
    asm("mov.b64 {%0, %1}, %2;" : "=f"(r.x), "=f"(r.y) : "l"(v));
    return r;
}
__device__ __forceinline__ void split_store(float v, __nv_bfloat16* hi, __nv_bfloat16* lo,
                                            size_t off) {
    __nv_bfloat16 h = __float2bfloat16(v);
    hi[off] = h;
    lo[off] = __float2bfloat16(v - __bfloat162float(h));
}

// ---------------- init ----------------
__global__ void k_zero() {
    int i = blockIdx.x*blockDim.x + threadIdx.x;
    float4 z = make_float4(0.f,0.f,0.f,0.f);
    if (i < NN16/4) { ((float4*)g_e)[i] = z; ((float4*)g_h)[i] = z; }
    if (i < NNODE) { g_D[i] = 0.f; g_B[i] = 0.f; }
    if (i < CIN) { g_sum[i] = 0.0; g_sum2[i] = 0.0; }
}

// ---------------- BatchNorm ----------------
__global__ void k_bnstats(const float* __restrict__ x) {
    __shared__ double sh[128], sh2[128];
    int b = blockIdx.x;
    const float* p = x + b*336;
    double s = 0.0, s2 = 0.0;
    for (int i = threadIdx.x; i < 336; i += 128) { double v = p[i]; s += v; s2 += v*v; }
    sh[threadIdx.x] = s; sh2[threadIdx.x] = s2; __syncthreads();
    for (int o = 64; o > 0; o >>= 1) {
        if (threadIdx.x < o) { sh[threadIdx.x] += sh[threadIdx.x+o]; sh2[threadIdx.x] += sh2[threadIdx.x+o]; }
        __syncthreads();
    }
    if (threadIdx.x == 0) {
        int c = b & 15;
        atomicAdd(&g_sum[c], sh[0]);
        atomicAdd(&g_sum2[c], sh2[0]);
    }
}

__global__ void k_bnfin(const float* __restrict__ gamma, const float* __restrict__ beta) {
    int c = threadIdx.x;
    if (c >= CIN) return;
    double cnt = (double)NNODE;
    double mean = g_sum[c] / cnt;
    double var  = g_sum2[c] / cnt - mean*mean;
    float sc = gamma[c] * rsqrtf((float)var + 1e-5f);
    g_scale[c] = sc;
    g_shift[c] = beta[c] - (float)mean * sc;
}

__global__ void k_bnx2(const float* __restrict__ x) {
    __shared__ float sx[16*337];
    const int n = blockIdx.x, tid = threadIdx.x;
    const float* xp = x + (size_t)n*5376;
    for (int i = tid; i < 5376; i += 256) {
        int c = i / 336, rem = i % 336;
        sx[c*337 + rem] = xp[i];
    }
    __syncthreads();
    const size_t base = (size_t)n*5376;
    for (int i = tid; i < 5376; i += 256) {
        int rem = i >> 4, c = i & 15;
        float v = sx[c*337 + rem];
        g_xn[base + i] = v;
        g_xb[base + i] = v * g_scale[c] + g_shift[c];
    }
}

// ---------------- hypergraph ----------------
__global__ void k_deg(const int* __restrict__ hi) {
    int i = blockIdx.x*blockDim.x + threadIdx.x;
    if (i >= EINC) return;
    atomicAdd(&g_D[hi[i]], 1.f);
    atomicAdd(&g_B[hi[EINC + i]], 1.f);
}

__global__ void k_inv() {
    int i = blockIdx.x*blockDim.x + threadIdx.x;
    if (i >= NNODE) return;
    float d = g_D[i]; g_D[i] = (d > 0.f) ? (1.f/d) : 0.f;
    float b = g_B[i]; g_B[i] = (b > 0.f) ? (1.f/b) : 0.f;
}

__global__ void k_scatter_e(const int* __restrict__ hi) {
    unsigned gi = blockIdx.x*blockDim.x + threadIdx.x;
    if (gi >= (unsigned)EINC * 4u) return;
    int i = (int)(gi >> 2), g = (int)((gi & 3u) << 2);
    int node = __ldg(&hi[i]), edge = __ldg(&hi[EINC + i]);
    float4 v = *(const float4*)(g_xn + (size_t)node*16 + g);
    float* dst = g_e + (size_t)edge*16 + g;
    asm volatile("red.global.add.v4.f32 [%0], {%1, %2, %3, %4};"
                 :: "l"(dst), "f"(v.x), "f"(v.y), "f"(v.z), "f"(v.w) : "memory");
}

__global__ void k_scatter_h(const int* __restrict__ hi) {
    unsigned gi = blockIdx.x*blockDim.x + threadIdx.x;
    if (gi >= (unsigned)EINC * 4u) return;
    int i = (int)(gi >> 2), g = (int)((gi & 3u) << 2);
    int node = __ldg(&hi[i]), edge = __ldg(&hi[EINC + i]);
    float w = g_B[edge];
    float4 v = *(const float4*)(g_e + (size_t)edge*16 + g);
    v.x *= w; v.y *= w; v.z *= w; v.w *= w;
    float* dst = g_h + (size_t)node*16 + g;
    asm volatile("red.global.add.v4.f32 [%0], {%1, %2, %3, %4};"
                 :: "l"(dst), "f"(v.x), "f"(v.y), "f"(v.z), "f"(v.w) : "memory");
}

// ---------------- fused hconv + time-conv -> seq (writes bf16 hi/lo directly) ----------------
__global__ __launch_bounds__(256) void k_seq2(
        const float* __restrict__ hcw, const float* __restrict__ hcb,
        const float* __restrict__ cw,  const float* __restrict__ cb) {
    __shared__ float sh_h[336*16];
    __shared__ float sh_w[16*64];
    __shared__ float sh_hv[336];
    __shared__ float sh_cw[64], sh_cb[8], sh_hcb[64];
    const int n = blockIdx.x, tid = threadIdx.x;
    const float4* hsrc = (const float4*)(g_h + (size_t)n*5376);
    const float* dsrc = g_D + n*336;
    for (int i = tid; i < 1344; i += 256) {
        float d = dsrc[i >> 2];
        float4 v = hsrc[i];
        v.x *= d; v.y *= d; v.z *= d; v.w *= d;
        *(float4*)(sh_h + 4*i) = v;
    }
    for (int i = tid; i < 1024; i += 256) {
        int co = i & 63, ci = i >> 6;
        sh_w[ci*64 + co] = hcw[co*16 + ci];
    }
    if (tid < 64) { sh_cw[tid] = cw[tid]; sh_hcb[tid] = hcb[tid]; }
    if (tid < 8)  sh_cb[tid] = cb[tid];

    for (int w = 0; w < 8; w++) {
        __syncthreads();
        for (int inner = tid; inner < 336; inner += 256) {
            int nodeL = w*42 + (inner >> 6);
            int c = inner & 63;
            const float* hr = sh_h + nodeL*16;
            float acc = sh_hcb[c];
            #pragma unroll
            for (int j = 0; j < 16; j++) acc += hr[j] * sh_w[j*64 + c];
            sh_hv[inner] = acc;
        }
        __syncthreads();
        for (int p = tid; p < 336; p += 256) {
            int o = p / 42, vm = p % 42;
            float acc = sh_cb[o];
            #pragma unroll
            for (int t = 0; t < 8; t++) acc += sh_cw[o*8 + t] * sh_hv[t*42 + vm];
            split_store(acc, g_seqh, g_seql, (size_t)(n*8 + o)*336 + w*42 + vm);
        }
    }
}

// ---------------- weight folding ----------------
__global__ void k_cw(const float* __restrict__ W1, const float* __restrict__ wq,
                     float* __restrict__ Wc) {
    int i = blockIdx.x*blockDim.x + threadIdx.x;
    if (i >= EMB*EMB) return;
    int o = i / EMB, ii = i % EMB;
    float acc = 0.f;
    for (int m = 0; m < EMB; m++) acc += W1[o*EMB + m] * wq[m*EMB + ii];
    Wc[i] = acc;
}

__global__ void k_cb(const float* __restrict__ W1, const float* __restrict__ b1,
                     const float* __restrict__ bq, float* __restrict__ bc) {
    int o = blockIdx.x*blockDim.x + threadIdx.x;
    if (o >= EMB) return;
    float acc = b1[o];
    for (int m = 0; m < EMB; m++) acc += W1[o*EMB + m] * bq[m];
    bc[o] = acc;
}

// ---------------- fp32 -> bf16 hi/lo (weights) ----------------
__global__ void k_prep(const float* __restrict__ src,
                       __nv_bfloat16* __restrict__ hi, __nv_bfloat16* __restrict__ lo,
                       int total_rows, int rows_src) {
    int i = blockIdx.x*blockDim.x + threadIdx.x;
    if (i >= total_rows*KDIM) return;
    int r = i / KDIM;
    float v = (r < rows_src) ? src[i] : 0.f;
    __nv_bfloat16 h = __float2bfloat16(v);
    hi[i] = h;
    lo[i] = __float2bfloat16(v - __bfloat162float(h));
}

// ---------------- mma.sync bf16 hi/lo GEMM, cp.async 3-stage ----------------
// MODE 0: fp32 C + bias.  MODE 1: fc fused residual+relu.  MODE 2: bf16 hi/lo out + bias.
#define STG3     3
#define BUFB     6144
#define ARRB     (STG3*BUFB)        // 18432
#define SMEM_DYN (4*ARRB + 4096 + 256)

template<int MODE>
__global__ __launch_bounds__(256) void k_gemm_mma(
        const __nv_bfloat16* __restrict__ Ah, const __nv_bfloat16* __restrict__ Al,
        const __nv_bfloat16* __restrict__ Bh, const __nv_bfloat16* __restrict__ Bl,
        const float* __restrict__ bias, float* __restrict__ C,
        __nv_bfloat16* __restrict__ Oh, __nv_bfloat16* __restrict__ Ol, int Nn,
        const float* __restrict__ pw, const float* __restrict__ pb) {
    extern __shared__ __align__(16) char dsm[];
    float* s_pw = (float*)(dsm + 4*ARRB);
    float* s_pb = s_pw + 1024;

    const int tid = threadIdx.x, lane = tid & 31, wid = tid >> 5;
    const int warpM = wid & 1, warpN = wid >> 1;
    const int row0 = blockIdx.y << 7, col0 = blockIdx.x << 7;

    if (MODE == 1) {
        for (int i = tid; i < 1024; i += 256) {
            int c = i >> 6, co = i & 63;
            s_pw[i] = pw[co*16 + c];
        }
        if (tid < 64) s_pb[tid] = pb[tid];
    }

    const int lrow = tid >> 1, lhalf = tid & 1;
    const __nv_bfloat16* gAh = Ah + (size_t)(row0 + lrow)*KDIM + lhalf*8;
    const __nv_bfloat16* gAl = Al + (size_t)(row0 + lrow)*KDIM + lhalf*8;
    const __nv_bfloat16* gBh = Bh + (size_t)(col0 + lrow)*KDIM + lhalf*8;
    const __nv_bfloat16* gBl = Bl + (size_t)(col0 + lrow)*KDIM + lhalf*8;
    const unsigned sb = smem_u32(dsm);
    const int so = lrow*48 + lhalf*16;

    const int rsubA = (lane & 7) + ((lane >> 3) & 1)*8;
    const int cA = (warpM*64 + rsubA)*48 + ((lane >> 4) & 1)*16;
    const int rsubB = (lane & 7) + ((lane >> 4) & 1)*8;
    const int cB = (warpN*32 + rsubB)*48 + ((lane >> 3) & 1)*16;

    float acc[4][4][4];
    #pragma unroll
    for (int i = 0; i < 4; i++)
        #pragma unroll
        for (int j = 0; j < 4; j++)
            #pragma unroll
            for (int q = 0; q < 4; q++) acc[i][j][q] = 0.f;

    // prologue: stages 0, 1
    #pragma unroll
    for (int st = 0; st < 2; st++) {
        unsigned d = sb + st*BUFB + so;
        cpa16(d,          gAh + st*16);
        cpa16(d + ARRB,   gAl + st*16);
        cpa16(d + 2*ARRB, gBh + st*16);
        cpa16(d + 3*ARRB, gBl + st*16);
        asm volatile("cp.async.commit_group;");
    }

    #pragma unroll 1
    for (int ch = 0; ch < NSTEP; ch++) {
        if (ch == NSTEP-1) asm volatile("cp.async.wait_group 0;");
        else               asm volatile("cp.async.wait_group 1;");
        __syncthreads();
        if (ch + 2 < NSTEP) {
            unsigned d = sb + ((ch+2)%3)*BUFB + so;
            cpa16(d,          gAh + (ch+2)*16);
            cpa16(d + ARRB,   gAl + (ch+2)*16);
            cpa16(d + 2*ARRB, gBh + (ch+2)*16);
            cpa16(d + 3*ARRB, gBl + (ch+2)*16);
            asm volatile("cp.async.commit_group;");
        }
        const unsigned bo = sb + (ch%3)*BUFB;
        unsigned AH[4][4], AL[4][4];
        #pragma unroll
        for (int mt = 0; mt < 4; mt++) {
            ldm4(AH[mt], bo + cA + mt*768);
            ldm4(AL[mt], bo + ARRB + cA + mt*768);
        }
        #pragma unroll
        for (int p = 0; p < 2; p++) {
            unsigned BH[4], BL[4];
            ldm4(BH, bo + 2*ARRB + cB + p*768);
            ldm4(BL, bo + 3*ARRB + cB + p*768);
            #pragma unroll
            for (int mt = 0; mt < 4; mt++) {
                #pragma unroll
                for (int q = 0; q < 2; q++) {
                    float* ac = acc[mt][2*p + q];
                    mma16816(ac, AH[mt], BH + 2*q);
                    mma16816(ac, AH[mt], BL + 2*q);
                    mma16816(ac, AL[mt], BH + 2*q);
                }
            }
        }
    }

    if (MODE == 0) {
        #pragma unroll
        for (int mt = 0; mt < 4; mt++) {
            int r1 = row0 + warpM*64 + mt*16 + (lane >> 2);
            #pragma unroll
            for (int nt = 0; nt < 4; nt++) {
                int gc = col0 + warpN*32 + nt*8 + (lane & 3)*2;
                if (gc < Nn) {
                    float b0 = __ldg(bias + gc), b1 = __ldg(bias + gc + 1);
                    float* ac = acc[mt][nt];
                    *(float2*)(C + (size_t)r1*Nn + gc)       = make_float2(ac[0]+b0, ac[1]+b1);
                    *(float2*)(C + (size_t)(r1+8)*Nn + gc)   = make_float2(ac[2]+b0, ac[3]+b1);
                }
            }
        }
    } else if (MODE == 2) {
        #pragma unroll
        for (int mt = 0; mt < 4; mt++) {
            int r1 = row0 + warpM*64 + mt*16 + (lane >> 2);
            #pragma unroll
            for (int nt = 0; nt < 4; nt++) {
                int gc = col0 + warpN*32 + nt*8 + (lane & 3)*2;
                if (gc < Nn) {
                    float b0 = __ldg(bias + gc), b1 = __ldg(bias + gc + 1);
                    float* ac = acc[mt][nt];
                    size_t o0 = (size_t)r1*KDIM + gc;
                    size_t o1 = (size_t)(r1+8)*KDIM + gc;
                    split_store(ac[0]+b0, Oh, Ol, o0);
                    split_store(ac[1]+b1, Oh, Ol, o0+1);
                    split_store(ac[2]+b0, Oh, Ol, o1);
                    split_store(ac[3]+b1, Oh, Ol, o1+1);
                }
            }
        }
    } else {
        __syncthreads();
        float* xs = (float*)dsm;
        const int v0 = col0 >> 6;
        for (int i = tid; i < 4096; i += 256) {
            int vml = i >> 11, r = (i >> 4) & 127, c = i & 15;
            xs[vml*2176 + r*17 + c] = g_xb[((size_t)(row0 + r)*42 + v0 + vml)*16 + c];
        }
        __syncthreads();

        const int vml = warpN >> 1;
        #pragma unroll
        for (int mt = 0; mt < 4; mt++) {
            int rl1 = warpM*64 + mt*16 + (lane >> 2);
            int rl2 = rl1 + 8;
            float xa[16], xc2[16];
            #pragma unroll
            for (int c = 0; c < 16; c++) {
                xa[c]  = xs[vml*2176 + rl1*17 + c];
                xc2[c] = xs[vml*2176 + rl2*17 + c];
            }
            #pragma unroll
            for (int nt = 0; nt < 4; nt++) {
                int co = (warpN & 1)*32 + nt*8 + (lane & 3)*2;
                int gc = col0 + (warpN & 1)*32 + (vml ? 64 : 0) + nt*8 + (lane & 3)*2;
                float fb0 = __ldg(bias + gc) + s_pb[co];
                float fb1 = __ldg(bias + gc + 1) + s_pb[co + 1];
                unsigned long long rv1 = pack2(fb0, fb1);
                unsigned long long rv2 = rv1;
                #pragma unroll
                for (int c = 0; c < 16; c++) {
                    unsigned long long w2 = *(const unsigned long long*)&s_pw[c*64 + co];
                    rv1 = ffma2(pack2(xa[c],  xa[c]),  w2, rv1);
                    rv2 = ffma2(pack2(xc2[c], xc2[c]), w2, rv2);
                }
                float2 u1 = unpack2(rv1), u2 = unpack2(rv2);
                float* ac = acc[mt][nt];
                int r1 = row0 + rl1, r2 = row0 + rl2;
                *(float2*)(C + (size_t)r1*2688 + gc) =
                    make_float2(fmaxf(ac[0]+u1.x, 0.f), fmaxf(ac[1]+u1.y, 0.f));
                *(float2*)(C + (size_t)r2*2688 + gc) =
                    make_float2(fmaxf(ac[2]+u2.x, 0.f), fmaxf(ac[3]+u2.y, 0.f));
            }
        }
    }
}

// ---------------- attention: block per sample, SMEM slab, hi/lo output ----------------
__global__ __launch_bounds__(256) void k_attn2() {
    __shared__ float sq[8*1012];
    __shared__ float sc[256], at[256];
    const int n = blockIdx.x, tid = threadIdx.x;
    const float* src = g_qkv + (size_t)n*8064;
    for (int i = tid; i < 8064; i += 256) {
        int r = i / 1008, c = i - r*1008;
        sq[r*1012 + c] = src[i];
    }
    __syncthreads();
    const int h = tid >> 6, s = (tid >> 3) & 7, t = tid & 7;
    {
        const float* qr = sq + s*1012 + h*84;
        const float* kr = sq + t*1012 + 336 + h*84;
        float acc = 0.f;
        #pragma unroll 12
        for (int d = 0; d < 84; d++) acc += qr[d]*kr[d];
        sc[tid] = acc * 0.1091089451179961805f;
    }
    __syncthreads();
    const int rb = tid & ~7;
    float mx = sc[rb];
    #pragma unroll
    for (int k = 1; k < 8; k++) mx = fmaxf(mx, sc[rb + k]);
    float e = expf(sc[tid] - mx);
    at[tid] = e;
    __syncthreads();
    float sum = 0.f;
    #pragma unroll
    for (int k = 0; k < 8; k++) sum += at[rb + k];
    float a = e / sum;
    __syncthreads();
    at[tid] = a;
    __syncthreads();
    for (int idx = tid; idx < 2688; idx += 256) {
        int s2 = idx / 336, c = idx - s2*336;
        int hh = c / 84, d = c - hh*84;
        const float* vr = sq + 672 + hh*84 + d;
        const float* ar = at + hh*64 + s2*8;
        float o = 0.f;
        #pragma unroll
        for (int k = 0; k < 8; k++) o += ar[k] * vr[k*1012];
        split_store(o, g_aoh, g_aol, (size_t)(n*8 + s2)*336 + c);
    }
}

// ---------------- launcher ----------------
extern "C" void kernel_launch(void* const* d_in, const int* in_sizes, int n_in,
                              void* d_out, int out_size) {
    const float* x   = (const float*)d_in[0];
    const int*   hi  = (const int*)  d_in[1];
    const float* hcw = (const float*)d_in[2];
    const float* hcb = (const float*)d_in[3];
    const float* cw  = (const float*)d_in[4];
    const float* cb  = (const float*)d_in[5];
    const float* gam = (const float*)d_in[6];
    const float* bet = (const float*)d_in[7];
    const float* pw  = (const float*)d_in[8];
    const float* pb  = (const float*)d_in[9];
    const float* wq  = (const float*)d_in[10];
    const float* bq  = (const float*)d_in[11];
    const float* wk  = (const float*)d_in[12];
    const float* bk  = (const float*)d_in[13];
    const float* wv  = (const float*)d_in[14];
    const float* bv  = (const float*)d_in[15];
    const float* ipw = (const float*)d_in[16];
    const float* ipb = (const float*)d_in[17];
    const float* opw = (const float*)d_in[18];
    const float* opb = (const float*)d_in[19];
    const float* fw  = (const float*)d_in[20];
    const float* fb  = (const float*)d_in[21];
    float* out = (float*)d_out;

    float *p_qkv, *p_Wc, *p_bc;
    cudaGetSymbolAddress((void**)&p_qkv, g_qkv);
    cudaGetSymbolAddress((void**)&p_Wc,  g_Wc);
    cudaGetSymbolAddress((void**)&p_bc,  g_bc);
    __nv_bfloat16 *p_seqh,*p_seql,*p_aoh,*p_aol,*p_o2h,*p_o2l,*p_wch,*p_wcl,*p_oph,*p_opl,*p_fwh,*p_fwl;
    cudaGetSymbolAddress((void**)&p_seqh, g_seqh); cudaGetSymbolAddress((void**)&p_seql, g_seql);
    cudaGetSymbolAddress((void**)&p_aoh,  g_aoh);  cudaGetSymbolAddress((void**)&p_aol,  g_aol);
    cudaGetSymbolAddress((void**)&p_o2h,  g_o2h);  cudaGetSymbolAddress((void**)&p_o2l,  g_o2l);
    cudaGetSymbolAddress((void**)&p_wch,  g_wch);  cudaGetSymbolAddress((void**)&p_wcl,  g_wcl);
    cudaGetSymbolAddress((void**)&p_oph,  g_oph);  cudaGetSymbolAddress((void**)&p_opl,  g_opl);
    cudaGetSymbolAddress((void**)&p_fwh,  g_fwh);  cudaGetSymbolAddress((void**)&p_fwl,  g_fwl);

    cudaFuncSetAttribute(k_gemm_mma<0>, cudaFuncAttributeMaxDynamicSharedMemorySize, SMEM_DYN);
    cudaFuncSetAttribute(k_gemm_mma<1>, cudaFuncAttributeMaxDynamicSharedMemorySize, SMEM_DYN);
    cudaFuncSetAttribute(k_gemm_mma<2>, cudaFuncAttributeMaxDynamicSharedMemorySize, SMEM_DYN);

    // graph path
    k_zero<<<(NN16/4 + 255)/256, 256>>>();
    k_bnstats<<<NB*CIN, 128>>>(x);
    k_bnfin<<<1, 32>>>(gam, bet);
    k_bnx2<<<NB, 256>>>(x);
    k_deg<<<(EINC + 255)/256, 256>>>(hi);
    k_inv<<<(NNODE + 255)/256, 256>>>();
    {
        long long tot = (long long)EINC * 4;
        int blocks = (int)((tot + 255) / 256);
        k_scatter_e<<<blocks, 256>>>(hi);
        k_scatter_h<<<blocks, 256>>>(hi);
    }
    k_seq2<<<NB, 256>>>(hcw, hcb, cw, cb);

    // weight folding + bf16 prep (weights only)
    k_cw<<<(EMB*EMB + 255)/256, 256>>>(ipw,             wq, p_Wc);
    k_cw<<<(EMB*EMB + 255)/256, 256>>>(ipw +   EMB*EMB, wk, p_Wc +   EMB*EMB);
    k_cw<<<(EMB*EMB + 255)/256, 256>>>(ipw + 2*EMB*EMB, wv, p_Wc + 2*EMB*EMB);
    k_cb<<<2, 256>>>(ipw,             ipb,         bq, p_bc);
    k_cb<<<2, 256>>>(ipw +   EMB*EMB, ipb +   EMB, bk, p_bc + EMB);
    k_cb<<<2, 256>>>(ipw + 2*EMB*EMB, ipb + 2*EMB, bv, p_bc + 2*EMB);
    k_prep<<<(1024*KDIM + 255)/256, 256>>>(p_Wc, p_wch, p_wcl, 1024, 1008);
    k_prep<<<(384*KDIM + 255)/256, 256>>>(opw, p_oph, p_opl, 384, 336);
    k_prep<<<(2688*KDIM + 255)/256, 256>>>(fw, p_fwh, p_fwl, 2688, 2688);

    // qkv: N=1008 -> fp32 g_qkv
    k_gemm_mma<0><<<dim3(8, ROWS/128), 256, SMEM_DYN>>>(
        p_seqh, p_seql, p_wch, p_wcl, p_bc, p_qkv, nullptr, nullptr, 1008, nullptr, nullptr);
    // attention -> aoh/aol (bf16 hi/lo)
    k_attn2<<<NB, 256>>>();
    // out_proj: N=336 -> o2h/o2l directly
    k_gemm_mma<2><<<dim3(3, ROWS/128), 256, SMEM_DYN>>>(
        p_aoh, p_aol, p_oph, p_opl, opb, nullptr, p_o2h, p_o2l, 336, nullptr, nullptr);
    // fc: N=2688 + fused residual + relu -> out
    k_gemm_mma<1><<<dim3(21, ROWS/128), 256, SMEM_DYN>>>(
        p_o2h, p_o2l, p_fwh, p_fwl, fb, out, nullptr, nullptr, 2688, pw, pb);
}